// round 9
// baseline (speedup 1.0000x reference)
#include <cuda_runtime.h>

#define BB 2
#define SS 2048
#define DD 2048
#define NHH 16
#define NKVV 4
#define HDD 128
#define QDIM 2048
#define KVDIM 512
#define QKVD 3072
#define MROWS (BB*SS)   // 4096

// fp32 scratch
__device__ float g_qkv[(size_t)MROWS * QKVD];
__device__ float g_attn[(size_t)MROWS * QDIM];

// packed bf16 hi/lo planes for projections (one u32 = 2 adjacent-k bf16)
__device__ unsigned g_xh[(size_t)MROWS * DD / 2],   g_xl[(size_t)MROWS * DD / 2];
__device__ unsigned g_wqh[(size_t)QKVD * DD / 2],   g_wql[(size_t)QKVD * DD / 2];
__device__ unsigned g_ah[(size_t)MROWS * QDIM / 2], g_al[(size_t)MROWS * QDIM / 2];
__device__ unsigned g_woh[(size_t)DD * QDIM / 2],   g_wol[(size_t)DD * QDIM / 2];

// attention operand planes (bf16 hi/lo packed words)
__device__ unsigned g_qh[(size_t)MROWS * QDIM / 2],  g_ql[(size_t)MROWS * QDIM / 2];
__device__ unsigned g_kh[(size_t)MROWS * KVDIM / 2], g_kl[(size_t)MROWS * KVDIM / 2];
__device__ unsigned g_vth[(size_t)BB * NKVV * HDD * SS / 2],
                    g_vtl[(size_t)BB * NKVV * HDD * SS / 2];

// ---------------------------------------------------------------------------
// helpers
// ---------------------------------------------------------------------------
__device__ __forceinline__ void mma_bf16(float* c, const unsigned* a, const unsigned* b) {
    asm volatile(
        "mma.sync.aligned.m16n8k16.row.col.f32.bf16.bf16.f32 "
        "{%0,%1,%2,%3},{%4,%5,%6,%7},{%8,%9},{%0,%1,%2,%3};"
        : "+f"(c[0]), "+f"(c[1]), "+f"(c[2]), "+f"(c[3])
        : "r"(a[0]), "r"(a[1]), "r"(a[2]), "r"(a[3]), "r"(b[0]), "r"(b[1]));
}

__device__ __forceinline__ void ldsm4(unsigned* r, unsigned addr) {
    asm volatile("ldmatrix.sync.aligned.m8n8.x4.shared.b16 {%0,%1,%2,%3}, [%4];"
                 : "=r"(r[0]), "=r"(r[1]), "=r"(r[2]), "=r"(r[3]) : "r"(addr));
}

__device__ __forceinline__ void cp16u(unsigned smem_dst, const void* gsrc) {
    asm volatile("cp.async.ca.shared.global [%0], [%1], 16;\n" :: "r"(smem_dst), "l"(gsrc));
}

__device__ __forceinline__ unsigned smem_u32(const void* p) {
    return (unsigned)__cvta_generic_to_shared(p);
}

// pack two fp32 (even, odd) into bf16 hi word + lo word (even -> low half)
__device__ __forceinline__ void pack_hilo(float p0, float p1, unsigned& hi, unsigned& lo) {
    unsigned u0 = __float_as_uint(p0), u1 = __float_as_uint(p1);
    asm("prmt.b32 %0, %1, %2, 0x7632;" : "=r"(hi) : "r"(u0), "r"(u1));
    float l0 = p0 - __uint_as_float(u0 & 0xffff0000u);
    float l1 = p1 - __uint_as_float(u1 & 0xffff0000u);
    asm("cvt.rn.satfinite.bf16x2.f32 %0, %1, %2;" : "=r"(lo) : "f"(l1), "f"(l0));
}

// ---------------------------------------------------------------------------
// Split fp32 -> packed bf16 hi/lo planes
// ---------------------------------------------------------------------------
__global__ __launch_bounds__(256) void split_kernel(
    const float4* __restrict__ in, uint2* __restrict__ hi, uint2* __restrict__ lo,
    int n4)
{
    int i = blockIdx.x * blockDim.x + threadIdx.x;
    if (i >= n4) return;
    float4 v = in[i];
    uint2 h, l;
    pack_hilo(v.x, v.y, h.x, l.x);
    pack_hilo(v.z, v.w, h.y, l.y);
    hi[i] = h;
    lo[i] = l;
}

// ---------------------------------------------------------------------------
// Pure-bf16 x3 NT GEMM on pre-split planes, ldmatrix fragment loads.
// (unchanged from R8 — verified)
// ---------------------------------------------------------------------------
#define PLANE_W (128 * 20)
#define STAGE_W (4 * PLANE_W)
#define GEMM_SMEM_BYTES (2 * STAGE_W * 4)
#define PLANE_B (PLANE_W * 4)
#define STAGE_B (STAGE_W * 4)

__global__ __launch_bounds__(256, 2) void gemm_planes_nt(
    const unsigned* __restrict__ Ah, const unsigned* __restrict__ Al,
    const unsigned* __restrict__ Bh, const unsigned* __restrict__ Bl,
    float* __restrict__ C, int M, int N, int K)
{
    extern __shared__ unsigned usm[];
    const int KW = K >> 1;

    int tid = threadIdx.x;
    int lane = tid & 31, w = tid >> 5;
    int wm = w >> 2, wn = w & 3;
    int g = lane >> 2, tc = lane & 3;
    int m0 = blockIdx.y * 128, n0 = blockIdx.x * 128;

    int lr = tid >> 2;
    int lw = (tid & 3) * 4;

    const unsigned* gp[4] = {
        Ah + (size_t)(m0 + lr) * KW + lw,
        Al + (size_t)(m0 + lr) * KW + lw,
        Bh + (size_t)(n0 + lr) * KW + lw,
        Bl + (size_t)(n0 + lr) * KW + lw };

    float acc[4][4][4] = {};

    auto load_stage = [&](int t, int buf) {
        unsigned* st = usm + buf * STAGE_W;
        size_t ko = (size_t)t * 16;
        #pragma unroll
        for (int p = 0; p < 4; p++) {
            #pragma unroll
            for (int r2 = 0; r2 < 2; r2++) {
                unsigned* d = st + p * PLANE_W + (lr + r2 * 64) * 20 + lw;
                cp16u((unsigned)__cvta_generic_to_shared(d),
                      gp[p] + (size_t)r2 * 64 * KW + ko);
            }
        }
        asm volatile("cp.async.commit_group;\n");
    };

    unsigned smem_base = smem_u32(usm);
    int arow = lane & 15;
    int akc  = (lane >> 4) & 1;
    int brow = (lane & 7) | (((lane >> 4) & 1) << 3);
    int bkc  = (lane >> 3) & 1;

    unsigned aH = smem_base + 0 * PLANE_B + (unsigned)((wm * 64 + arow) * 80 + akc * 16);
    unsigned aL = aH + PLANE_B;
    unsigned bH = smem_base + 2 * PLANE_B + (unsigned)((wn * 32 + brow) * 80 + bkc * 16);
    unsigned bL = bH + PLANE_B;

    int T = K / 32;
    load_stage(0, 0);

    for (int t = 0; t < T; t++) {
        asm volatile("cp.async.wait_group 0;\n");
        __syncthreads();
        if (t + 1 < T) load_stage(t + 1, (t + 1) & 1);

        unsigned stg = (t & 1) * STAGE_B;

        #pragma unroll
        for (int ks = 0; ks < 2; ks++) {
            unsigned ah[4][4], al[4][4], bhp[2][4], blp[2][4];
            unsigned kso = stg + ks * 32;
            #pragma unroll
            for (int mf = 0; mf < 4; mf++) {
                ldsm4(ah[mf], aH + kso + mf * 1280);
                ldsm4(al[mf], aL + kso + mf * 1280);
            }
            #pragma unroll
            for (int p = 0; p < 2; p++) {
                ldsm4(bhp[p], bH + kso + p * 1280);
                ldsm4(blp[p], bL + kso + p * 1280);
            }
            #pragma unroll
            for (int mf = 0; mf < 4; mf++)
                #pragma unroll
                for (int nf = 0; nf < 4; nf++) {
                    const unsigned* bhf = &bhp[nf >> 1][(nf & 1) * 2];
                    const unsigned* blf = &blp[nf >> 1][(nf & 1) * 2];
                    mma_bf16(acc[mf][nf], ah[mf], bhf);
                    mma_bf16(acc[mf][nf], ah[mf], blf);
                    mma_bf16(acc[mf][nf], al[mf], bhf);
                }
        }
        __syncthreads();
    }

    #pragma unroll
    for (int mf = 0; mf < 4; mf++) {
        #pragma unroll
        for (int nf = 0; nf < 4; nf++) {
            int row = m0 + wm * 64 + mf * 16 + g;
            int col = n0 + wn * 32 + nf * 8 + 2 * tc;
            *(float2*)(C + (size_t)row * N + col) =
                make_float2(acc[mf][nf][0], acc[mf][nf][1]);
            *(float2*)(C + (size_t)(row + 8) * N + col) =
                make_float2(acc[mf][nf][2], acc[mf][nf][3]);
        }
    }
}

// ---------------------------------------------------------------------------
// RoPE on q,k -> packed bf16 hi/lo planes.
// ---------------------------------------------------------------------------
__global__ __launch_bounds__(256) void rope_qk_kernel(
    const float* __restrict__ qkv, const float* __restrict__ freqs,
    unsigned* __restrict__ qh, unsigned* __restrict__ ql,
    unsigned* __restrict__ kh, unsigned* __restrict__ kl)
{
    int idx = blockIdx.x * blockDim.x + threadIdx.x;
    int i    = idx & 63;
    int head = (idx >> 6) % 20;
    int bs   = idx / (64 * 20);
    int s    = bs & (SS - 1);

    int off = (head < NHH) ? head * HDD : QDIM + (head - NHH) * HDD;
    size_t base = (size_t)bs * QKVD + off + 2 * i;
    float t0 = qkv[base], t1 = qkv[base + 1];
    float f0 = freqs[s * HDD + 2 * i];
    float f1 = freqs[s * HDD + 2 * i + 1];
    float r0 = t0 * f1 - t1 * f0;      // even element
    float r1 = t0 * f0 + t1 * f1;      // odd element
    unsigned hi, lo;
    pack_hilo(r0, r1, hi, lo);
    if (head < NHH) {
        size_t o = (size_t)bs * (QDIM / 2) + head * 64 + i;
        qh[o] = hi; ql[o] = lo;
    } else {
        size_t o = (size_t)bs * (KVDIM / 2) + (head - NHH) * 64 + i;
        kh[o] = hi; kl[o] = lo;
    }
}

// ---------------------------------------------------------------------------
// V pack + transpose: g_qkv v-section -> vt[b][kvh][hd][s] bf16 hi/lo words.
// ---------------------------------------------------------------------------
__global__ __launch_bounds__(256) void vpack_kernel(
    const float* __restrict__ qkv, unsigned* __restrict__ vth, unsigned* __restrict__ vtl)
{
    int idx = blockIdx.x * blockDim.x + threadIdx.x;   // BB*NKVV*HDD*(SS/2)
    int s2  = idx & (SS / 2 - 1);
    int hd  = (idx >> 10) & (HDD - 1);
    int kvh = (idx >> 17) & (NKVV - 1);
    int b   = idx >> 19;

    const float* src = qkv + (size_t)(b * SS + 2 * s2) * QKVD
                           + QDIM + KVDIM + kvh * HDD + hd;
    float v0 = src[0], v1 = src[QKVD];
    unsigned hi, lo;
    pack_hilo(v0, v1, hi, lo);
    size_t o = ((size_t)((b * NKVV + kvh) * HDD + hd)) * (SS / 2) + s2;
    vth[o] = hi; vtl[o] = lo;
}

// ---------------------------------------------------------------------------
// Causal flash attention, bf16x3 mma + ldmatrix, register softmax.
// 128 q-rows/CTA, 64 k-cols/iter. 8 warps x 16 rows.
// smem (bytes): Qh 0, Ql 34816, K[buf][plane] @69632 (17408 each),
//               Vh 139264, Vl 157696, Ph 176128, Pl 194560. total 212992.
// Row strides: Q/K 272 B (17x16), V/P 144 B (9x16) -> ldsm conflict-free.
// ---------------------------------------------------------------------------
#define ATT_SMEM_BYTES 212992

__global__ __launch_bounds__(256, 1) void attn_bf16_kernel(
    const unsigned* __restrict__ qh, const unsigned* __restrict__ ql,
    const unsigned* __restrict__ kh, const unsigned* __restrict__ kl,
    const unsigned* __restrict__ vth, const unsigned* __restrict__ vtl,
    float* __restrict__ attn)
{
    extern __shared__ __align__(16) unsigned char dynsm[];
    unsigned sb = smem_u32(dynsm);

    int tid = threadIdx.x;
    int lane = tid & 31, w = tid >> 5;
    int g = lane >> 2, tc = lane & 3;
    int qt = (SS / 128 - 1) - blockIdx.x;
    int h  = blockIdx.y, b = blockIdx.z;
    int kvh = h >> 2;
    int q0 = qt * 128;
    int ktmax = 2 * qt + 1;
    const float scale = 0.08838834764831845f;

    auto issueK = [&](int kt) {
        if (kt <= ktmax) {
            unsigned dst0 = sb + 69632u + (kt & 1) * 34816u;
            #pragma unroll
            for (int e = 0; e < 8; e++) {
                int i = tid + e * 256;
                int plane = i >> 10, j = i & 1023;
                int r = j >> 4, c = j & 15;
                const unsigned* src = (plane ? kl : kh)
                    + (size_t)(b * SS + kt * 64 + r) * (KVDIM / 2) + kvh * 64 + c * 4;
                cp16u(dst0 + plane * 17408u + r * 272u + c * 16u, src);
            }
        }
        asm volatile("cp.async.commit_group;\n");
    };
    auto issueV = [&](int kt) {
        #pragma unroll
        for (int e = 0; e < 8; e++) {
            int i = tid + e * 256;
            int plane = i >> 10, j = i & 1023;
            int r = j >> 3, c = j & 7;
            const unsigned* src = (plane ? vtl : vth)
                + ((size_t)((b * NKVV + kvh) * HDD + r)) * (SS / 2) + kt * 32 + c * 4;
            cp16u(sb + 139264u + plane * 18432u + r * 144u + c * 16u, src);
        }
        asm volatile("cp.async.commit_group;\n");
    };

    // prologue: [Q + K0] as one group
    {
        #pragma unroll
        for (int e = 0; e < 16; e++) {
            int i = tid + e * 256;
            int plane = i >> 11, j = i & 2047;
            int r = j >> 4, c = j & 15;
            const unsigned* src = (plane ? ql : qh)
                + (size_t)(b * SS + q0 + r) * (QDIM / 2) + h * 64 + c * 4;
            cp16u(sb + plane * 34816u + r * 272u + c * 16u, src);
        }
        unsigned dst0 = sb + 69632u;
        #pragma unroll
        for (int e = 0; e < 8; e++) {
            int i = tid + e * 256;
            int plane = i >> 10, j = i & 1023;
            int r = j >> 4, c = j & 15;
            const unsigned* src = (plane ? kl : kh)
                + (size_t)(b * SS + r) * (KVDIM / 2) + kvh * 64 + c * 4;
            cp16u(dst0 + plane * 17408u + r * 272u + c * 16u, src);
        }
        asm volatile("cp.async.commit_group;\n");
    }

    // fragment address components (verified layout from gemm_planes_nt)
    int arow = lane & 15;
    int akc  = (lane >> 4) & 1;
    int brow = (lane & 7) | (((lane >> 4) & 1) << 3);
    int bkc  = (lane >> 3) & 1;

    unsigned aQh = sb + (unsigned)((w * 16 + arow) * 272 + akc * 16);
    unsigned aQl = aQh + 34816u;
    unsigned bKo = (unsigned)(brow * 272 + bkc * 16);          // + buf/plane/nblk
    unsigned aPh = sb + 176128u + (unsigned)((w * 16 + arow) * 144 + akc * 16);
    unsigned aPl = aPh + 18432u;
    unsigned bVh = sb + 139264u + (unsigned)(brow * 144 + bkc * 16);

    float m0r = -1e30f, m1r = -1e30f, l0r = 0.f, l1r = 0.f;
    float acc[16][4];
    #pragma unroll
    for (int nf = 0; nf < 16; nf++)
        #pragma unroll
        for (int r = 0; r < 4; r++) acc[nf][r] = 0.f;

    int srow = w * 16 + g;

    for (int kt = 0; kt <= ktmax; kt++) {
        __syncthreads();                 // A: prev iter done (sV, sK[(kt+1)&1] free)
        issueV(kt);
        issueK(kt + 1);

        asm volatile("cp.async.wait_group 2;\n");   // K[kt] ready
        __syncthreads();                 // B

        // ---- S = Q K^T (bf16 x3) ----
        float sacc[8][4] = {};
        unsigned bK = sb + 69632u + (kt & 1) * 34816u + bKo;
        #pragma unroll
        for (int ks = 0; ks < 8; ks++) {
            unsigned qhf[4], qlf[4];
            ldsm4(qhf, aQh + ks * 32);
            ldsm4(qlf, aQl + ks * 32);
            #pragma unroll
            for (int nblk = 0; nblk < 4; nblk++) {
                unsigned khf[4], klf[4];
                unsigned ka = bK + nblk * 4352u + ks * 32;
                ldsm4(khf, ka);
                ldsm4(klf, ka + 17408u);
                #pragma unroll
                for (int sub = 0; sub < 2; sub++) {
                    float* c = sacc[nblk * 2 + sub];
                    const unsigned* bh2 = &khf[sub * 2];
                    const unsigned* bl2 = &klf[sub * 2];
                    mma_bf16(c, qhf, bh2);
                    mma_bf16(c, qhf, bl2);
                    mma_bf16(c, qlf, bh2);
                }
            }
        }

        // ---- scale + causal mask ----
        {
            int k0 = kt * 64;
            bool diag = (kt >= 2 * qt);
            #pragma unroll
            for (int nf = 0; nf < 8; nf++) {
                float v0 = sacc[nf][0] * scale, v1 = sacc[nf][1] * scale;
                float v2 = sacc[nf][2] * scale, v3 = sacc[nf][3] * scale;
                if (diag) {
                    int qr = q0 + srow, kc = k0 + nf * 8 + 2 * tc;
                    if (kc     > qr)     v0 = -1e30f;
                    if (kc + 1 > qr)     v1 = -1e30f;
                    if (kc     > qr + 8) v2 = -1e30f;
                    if (kc + 1 > qr + 8) v3 = -1e30f;
                }
                sacc[nf][0] = v0; sacc[nf][1] = v1;
                sacc[nf][2] = v2; sacc[nf][3] = v3;
            }
        }

        // ---- register softmax; P packed to bf16 hi/lo planes ----
        float alpha0, alpha1;
        {
            float mx0 = -1e30f, mx1 = -1e30f;
            #pragma unroll
            for (int nf = 0; nf < 8; nf++) {
                mx0 = fmaxf(mx0, fmaxf(sacc[nf][0], sacc[nf][1]));
                mx1 = fmaxf(mx1, fmaxf(sacc[nf][2], sacc[nf][3]));
            }
            mx0 = fmaxf(mx0, __shfl_xor_sync(0xffffffffu, mx0, 1));
            mx0 = fmaxf(mx0, __shfl_xor_sync(0xffffffffu, mx0, 2));
            mx1 = fmaxf(mx1, __shfl_xor_sync(0xffffffffu, mx1, 1));
            mx1 = fmaxf(mx1, __shfl_xor_sync(0xffffffffu, mx1, 2));

            float mn0 = fmaxf(m0r, mx0), mn1 = fmaxf(m1r, mx1);
            alpha0 = __expf(m0r - mn0);
            alpha1 = __expf(m1r - mn1);

            unsigned pr0 = sb + 176128u + srow * 144u;
            unsigned pr1 = pr0 + 8 * 144u;
            float s0 = 0.f, s1 = 0.f;
            #pragma unroll
            for (int nf = 0; nf < 8; nf++) {
                float p0 = __expf(sacc[nf][0] - mn0);
                float p1 = __expf(sacc[nf][1] - mn0);
                float p2 = __expf(sacc[nf][2] - mn1);
                float p3 = __expf(sacc[nf][3] - mn1);
                s0 += p0 + p1;
                s1 += p2 + p3;
                unsigned hi, lo;
                unsigned wo = (nf * 4 + tc) * 4;
                pack_hilo(p0, p1, hi, lo);
                asm volatile("st.shared.b32 [%0], %1;" :: "r"(pr0 + wo), "r"(hi));
                asm volatile("st.shared.b32 [%0], %1;" :: "r"(pr0 + wo + 18432u), "r"(lo));
                pack_hilo(p2, p3, hi, lo);
                asm volatile("st.shared.b32 [%0], %1;" :: "r"(pr1 + wo), "r"(hi));
                asm volatile("st.shared.b32 [%0], %1;" :: "r"(pr1 + wo + 18432u), "r"(lo));
            }
            s0 += __shfl_xor_sync(0xffffffffu, s0, 1);
            s0 += __shfl_xor_sync(0xffffffffu, s0, 2);
            s1 += __shfl_xor_sync(0xffffffffu, s1, 1);
            s1 += __shfl_xor_sync(0xffffffffu, s1, 2);
            l0r = l0r * alpha0 + s0;
            l1r = l1r * alpha1 + s1;
            m0r = mn0; m1r = mn1;
        }
        __syncwarp();                    // P warp-private

        // ---- rescale O ----
        #pragma unroll
        for (int nf = 0; nf < 16; nf++) {
            acc[nf][0] *= alpha0; acc[nf][1] *= alpha0;
            acc[nf][2] *= alpha1; acc[nf][3] *= alpha1;
        }

        asm volatile("cp.async.wait_group 1;\n");   // V[kt] ready
        __syncthreads();                 // C

        // ---- O += P V (bf16 x3) ----
        #pragma unroll
        for (int ks = 0; ks < 4; ks++) {
            unsigned phf[4], plf[4];
            ldsm4(phf, aPh + ks * 32);
            ldsm4(plf, aPl + ks * 32);
            #pragma unroll
            for (int nblk = 0; nblk < 8; nblk++) {
                unsigned vhf[4], vlf[4];
                unsigned va = bVh + nblk * 2304u + ks * 32;
                ldsm4(vhf, va);
                ldsm4(vlf, va + 18432u);
                #pragma unroll
                for (int sub = 0; sub < 2; sub++) {
                    float* c = acc[nblk * 2 + sub];
                    const unsigned* bh2 = &vhf[sub * 2];
                    const unsigned* bl2 = &vlf[sub * 2];
                    mma_bf16(c, phf, bh2);
                    mma_bf16(c, phf, bl2);
                    mma_bf16(c, plf, bh2);
                }
            }
        }
    }

    // ---- epilogue ----
    float inv0 = 1.f / l0r;
    float inv1 = 1.f / l1r;
    int row = q0 + srow;
    float* ob = attn + ((size_t)(b * SS + row)) * QDIM + h * HDD;
    #pragma unroll
    for (int nf = 0; nf < 16; nf++) {
        *(float2*)(ob + nf * 8 + 2 * tc) =
            make_float2(acc[nf][0] * inv0, acc[nf][1] * inv0);
        *(float2*)(ob + (size_t)8 * QDIM + nf * 8 + 2 * tc) =
            make_float2(acc[nf][2] * inv1, acc[nf][3] * inv1);
    }
}

// ---------------------------------------------------------------------------
extern "C" void kernel_launch(void* const* d_in, const int* in_sizes, int n_in,
                              void* d_out, int out_size)
{
    (void)in_sizes; (void)n_in; (void)out_size;
    const float* x     = (const float*)d_in[0];
    const float* freqs = (const float*)d_in[1];
    const float* Wqkv  = (const float*)d_in[2];
    const float* Wo    = (const float*)d_in[3];
    float* out = (float*)d_out;

    float *qkvp, *attnp;
    unsigned *xh, *xl, *wqh, *wql, *ah, *al, *woh, *wol;
    unsigned *qh, *ql, *kh, *kl, *vth, *vtl;
    cudaGetSymbolAddress((void**)&qkvp, g_qkv);
    cudaGetSymbolAddress((void**)&attnp, g_attn);
    cudaGetSymbolAddress((void**)&xh, g_xh);   cudaGetSymbolAddress((void**)&xl, g_xl);
    cudaGetSymbolAddress((void**)&wqh, g_wqh); cudaGetSymbolAddress((void**)&wql, g_wql);
    cudaGetSymbolAddress((void**)&ah, g_ah);   cudaGetSymbolAddress((void**)&al, g_al);
    cudaGetSymbolAddress((void**)&woh, g_woh); cudaGetSymbolAddress((void**)&wol, g_wol);
    cudaGetSymbolAddress((void**)&qh, g_qh);   cudaGetSymbolAddress((void**)&ql, g_ql);
    cudaGetSymbolAddress((void**)&kh, g_kh);   cudaGetSymbolAddress((void**)&kl, g_kl);
    cudaGetSymbolAddress((void**)&vth, g_vth); cudaGetSymbolAddress((void**)&vtl, g_vtl);

    cudaFuncSetAttribute(attn_bf16_kernel, cudaFuncAttributeMaxDynamicSharedMemorySize,
                         ATT_SMEM_BYTES);
    cudaFuncSetAttribute(gemm_planes_nt, cudaFuncAttributeMaxDynamicSharedMemorySize,
                         GEMM_SMEM_BYTES);

    // 0) split inputs into bf16 hi/lo planes
    {
        int n4;
        n4 = MROWS * DD / 4;
        split_kernel<<<n4 / 256, 256>>>((const float4*)x, (uint2*)xh, (uint2*)xl, n4);
        n4 = QKVD * DD / 4;
        split_kernel<<<n4 / 256, 256>>>((const float4*)Wqkv, (uint2*)wqh, (uint2*)wql, n4);
        n4 = DD * QDIM / 4;
        split_kernel<<<n4 / 256, 256>>>((const float4*)Wo, (uint2*)woh, (uint2*)wol, n4);
    }

    // 1) QKV projection (bf16x3, ldmatrix)
    gemm_planes_nt<<<dim3(QKVD / 128, MROWS / 128), 256, GEMM_SMEM_BYTES>>>(
        xh, xl, wqh, wql, qkvp, MROWS, QKVD, DD);

    // 2) RoPE -> q/k bf16 planes; V transpose+pack
    rope_qk_kernel<<<(BB * SS * 20 * 64) / 256, 256>>>(qkvp, freqs, qh, ql, kh, kl);
    vpack_kernel<<<(BB * NKVV * HDD * (SS / 2)) / 256, 256>>>(qkvp, vth, vtl);

    // 3) causal GQA flash attention (bf16x3 + ldmatrix)
    attn_bf16_kernel<<<dim3(SS / 128, NHH, BB), 256, ATT_SMEM_BYTES>>>(
        qh, ql, kh, kl, vth, vtl, attnp);

    // 3b) split attention output
    {
        int n4 = MROWS * QDIM / 4;
        split_kernel<<<n4 / 256, 256>>>((const float4*)attnp, (uint2*)ah, (uint2*)al, n4);
    }

    // 4) output projection (bf16x3, ldmatrix)
    gemm_planes_nt<<<dim3(DD / 128, MROWS / 128), 256, GEMM_SMEM_BYTES>>>(
        ah, al, woh, wol, out, MROWS, DD, QDIM);
}

// round 10
// speedup vs baseline: 1.0502x; 1.0502x over previous
#include <cuda_runtime.h>

#define BB 2
#define SS 2048
#define DD 2048
#define NHH 16
#define NKVV 4
#define HDD 128
#define QDIM 2048
#define KVDIM 512
#define QKVD 3072
#define MROWS (BB*SS)   // 4096

// fp32 scratch
__device__ float g_qkv[(size_t)MROWS * QKVD];

// packed bf16 hi/lo planes for projections (one u32 = 2 adjacent-k bf16)
__device__ unsigned g_xh[(size_t)MROWS * DD / 2],   g_xl[(size_t)MROWS * DD / 2];
__device__ unsigned g_wqh[(size_t)QKVD * DD / 2],   g_wql[(size_t)QKVD * DD / 2];
__device__ unsigned g_ah[(size_t)MROWS * QDIM / 2], g_al[(size_t)MROWS * QDIM / 2];
__device__ unsigned g_woh[(size_t)DD * QDIM / 2],   g_wol[(size_t)DD * QDIM / 2];

// attention operand planes (bf16 hi/lo packed words)
__device__ unsigned g_qh[(size_t)MROWS * QDIM / 2],  g_ql[(size_t)MROWS * QDIM / 2];
__device__ unsigned g_kh[(size_t)MROWS * KVDIM / 2], g_kl[(size_t)MROWS * KVDIM / 2];
__device__ unsigned g_vth[(size_t)BB * NKVV * HDD * SS / 2],
                    g_vtl[(size_t)BB * NKVV * HDD * SS / 2];

// ---------------------------------------------------------------------------
// helpers
// ---------------------------------------------------------------------------
__device__ __forceinline__ void mma_bf16(float* c, const unsigned* a, const unsigned* b) {
    asm volatile(
        "mma.sync.aligned.m16n8k16.row.col.f32.bf16.bf16.f32 "
        "{%0,%1,%2,%3},{%4,%5,%6,%7},{%8,%9},{%0,%1,%2,%3};"
        : "+f"(c[0]), "+f"(c[1]), "+f"(c[2]), "+f"(c[3])
        : "r"(a[0]), "r"(a[1]), "r"(a[2]), "r"(a[3]), "r"(b[0]), "r"(b[1]));
}

__device__ __forceinline__ void ldsm4(unsigned* r, unsigned addr) {
    asm volatile("ldmatrix.sync.aligned.m8n8.x4.shared.b16 {%0,%1,%2,%3}, [%4];"
                 : "=r"(r[0]), "=r"(r[1]), "=r"(r[2]), "=r"(r[3]) : "r"(addr));
}

__device__ __forceinline__ void cp16u(unsigned smem_dst, const void* gsrc) {
    asm volatile("cp.async.ca.shared.global [%0], [%1], 16;\n" :: "r"(smem_dst), "l"(gsrc));
}

__device__ __forceinline__ unsigned smem_u32(const void* p) {
    return (unsigned)__cvta_generic_to_shared(p);
}

// pack two fp32 (even, odd) into bf16 hi word + lo word (even -> low half)
__device__ __forceinline__ void pack_hilo(float p0, float p1, unsigned& hi, unsigned& lo) {
    unsigned u0 = __float_as_uint(p0), u1 = __float_as_uint(p1);
    asm("prmt.b32 %0, %1, %2, 0x7632;" : "=r"(hi) : "r"(u0), "r"(u1));
    float l0 = p0 - __uint_as_float(u0 & 0xffff0000u);
    float l1 = p1 - __uint_as_float(u1 & 0xffff0000u);
    asm("cvt.rn.satfinite.bf16x2.f32 %0, %1, %2;" : "=r"(lo) : "f"(l1), "f"(l0));
}

__device__ __forceinline__ unsigned pack_rn(float p0, float p1) {
    unsigned r;
    asm("cvt.rn.satfinite.bf16x2.f32 %0, %1, %2;" : "=r"(r) : "f"(p1), "f"(p0));
    return r;
}

// ---------------------------------------------------------------------------
// Split fp32 -> packed bf16 hi/lo planes
// ---------------------------------------------------------------------------
__global__ __launch_bounds__(256) void split_kernel(
    const float4* __restrict__ in, uint2* __restrict__ hi, uint2* __restrict__ lo,
    int n4)
{
    int i = blockIdx.x * blockDim.x + threadIdx.x;
    if (i >= n4) return;
    float4 v = in[i];
    uint2 h, l;
    pack_hilo(v.x, v.y, h.x, l.x);
    pack_hilo(v.z, v.w, h.y, l.y);
    hi[i] = h;
    lo[i] = l;
}

// ---------------------------------------------------------------------------
// Pure-bf16 x3 NT GEMM on pre-split planes, ldmatrix fragment loads.
// (unchanged from R8/R9 — at legacy-HMMA ceiling)
// ---------------------------------------------------------------------------
#define PLANE_W (128 * 20)
#define STAGE_W (4 * PLANE_W)
#define GEMM_SMEM_BYTES (2 * STAGE_W * 4)
#define PLANE_B (PLANE_W * 4)
#define STAGE_B (STAGE_W * 4)

__global__ __launch_bounds__(256, 2) void gemm_planes_nt(
    const unsigned* __restrict__ Ah, const unsigned* __restrict__ Al,
    const unsigned* __restrict__ Bh, const unsigned* __restrict__ Bl,
    float* __restrict__ C, int M, int N, int K)
{
    extern __shared__ unsigned usm[];
    const int KW = K >> 1;

    int tid = threadIdx.x;
    int lane = tid & 31, w = tid >> 5;
    int wm = w >> 2, wn = w & 3;
    int g = lane >> 2, tc = lane & 3;
    int m0 = blockIdx.y * 128, n0 = blockIdx.x * 128;

    int lr = tid >> 2;
    int lw = (tid & 3) * 4;

    const unsigned* gp[4] = {
        Ah + (size_t)(m0 + lr) * KW + lw,
        Al + (size_t)(m0 + lr) * KW + lw,
        Bh + (size_t)(n0 + lr) * KW + lw,
        Bl + (size_t)(n0 + lr) * KW + lw };

    float acc[4][4][4] = {};

    auto load_stage = [&](int t, int buf) {
        unsigned* st = usm + buf * STAGE_W;
        size_t ko = (size_t)t * 16;
        #pragma unroll
        for (int p = 0; p < 4; p++) {
            #pragma unroll
            for (int r2 = 0; r2 < 2; r2++) {
                unsigned* d = st + p * PLANE_W + (lr + r2 * 64) * 20 + lw;
                cp16u((unsigned)__cvta_generic_to_shared(d),
                      gp[p] + (size_t)r2 * 64 * KW + ko);
            }
        }
        asm volatile("cp.async.commit_group;\n");
    };

    unsigned smem_base = smem_u32(usm);
    int arow = lane & 15;
    int akc  = (lane >> 4) & 1;
    int brow = (lane & 7) | (((lane >> 4) & 1) << 3);
    int bkc  = (lane >> 3) & 1;

    unsigned aH = smem_base + 0 * PLANE_B + (unsigned)((wm * 64 + arow) * 80 + akc * 16);
    unsigned aL = aH + PLANE_B;
    unsigned bH = smem_base + 2 * PLANE_B + (unsigned)((wn * 32 + brow) * 80 + bkc * 16);
    unsigned bL = bH + PLANE_B;

    int T = K / 32;
    load_stage(0, 0);

    for (int t = 0; t < T; t++) {
        asm volatile("cp.async.wait_group 0;\n");
        __syncthreads();
        if (t + 1 < T) load_stage(t + 1, (t + 1) & 1);

        unsigned stg = (t & 1) * STAGE_B;

        #pragma unroll
        for (int ks = 0; ks < 2; ks++) {
            unsigned ah[4][4], al[4][4], bhp[2][4], blp[2][4];
            unsigned kso = stg + ks * 32;
            #pragma unroll
            for (int mf = 0; mf < 4; mf++) {
                ldsm4(ah[mf], aH + kso + mf * 1280);
                ldsm4(al[mf], aL + kso + mf * 1280);
            }
            #pragma unroll
            for (int p = 0; p < 2; p++) {
                ldsm4(bhp[p], bH + kso + p * 1280);
                ldsm4(blp[p], bL + kso + p * 1280);
            }
            #pragma unroll
            for (int mf = 0; mf < 4; mf++)
                #pragma unroll
                for (int nf = 0; nf < 4; nf++) {
                    const unsigned* bhf = &bhp[nf >> 1][(nf & 1) * 2];
                    const unsigned* blf = &blp[nf >> 1][(nf & 1) * 2];
                    mma_bf16(acc[mf][nf], ah[mf], bhf);
                    mma_bf16(acc[mf][nf], ah[mf], blf);
                    mma_bf16(acc[mf][nf], al[mf], bhf);
                }
        }
        __syncthreads();
    }

    #pragma unroll
    for (int mf = 0; mf < 4; mf++) {
        #pragma unroll
        for (int nf = 0; nf < 4; nf++) {
            int row = m0 + wm * 64 + mf * 16 + g;
            int col = n0 + wn * 32 + nf * 8 + 2 * tc;
            *(float2*)(C + (size_t)row * N + col) =
                make_float2(acc[mf][nf][0], acc[mf][nf][1]);
            *(float2*)(C + (size_t)(row + 8) * N + col) =
                make_float2(acc[mf][nf][2], acc[mf][nf][3]);
        }
    }
}

// ---------------------------------------------------------------------------
// RoPE on q,k -> packed bf16 hi/lo planes.
// ---------------------------------------------------------------------------
__global__ __launch_bounds__(256) void rope_qk_kernel(
    const float* __restrict__ qkv, const float* __restrict__ freqs,
    unsigned* __restrict__ qh, unsigned* __restrict__ ql,
    unsigned* __restrict__ kh, unsigned* __restrict__ kl)
{
    int idx = blockIdx.x * blockDim.x + threadIdx.x;
    int i    = idx & 63;
    int head = (idx >> 6) % 20;
    int bs   = idx / (64 * 20);
    int s    = bs & (SS - 1);

    int off = (head < NHH) ? head * HDD : QDIM + (head - NHH) * HDD;
    size_t base = (size_t)bs * QKVD + off + 2 * i;
    float t0 = qkv[base], t1 = qkv[base + 1];
    float f0 = freqs[s * HDD + 2 * i];
    float f1 = freqs[s * HDD + 2 * i + 1];
    float r0 = t0 * f1 - t1 * f0;
    float r1 = t0 * f0 + t1 * f1;
    unsigned hi, lo;
    pack_hilo(r0, r1, hi, lo);
    if (head < NHH) {
        size_t o = (size_t)bs * (QDIM / 2) + head * 64 + i;
        qh[o] = hi; ql[o] = lo;
    } else {
        size_t o = (size_t)bs * (KVDIM / 2) + (head - NHH) * 64 + i;
        kh[o] = hi; kl[o] = lo;
    }
}

// ---------------------------------------------------------------------------
// V pack + transpose: g_qkv v-section -> vt[b][kvh][hd][s] bf16 hi/lo words.
// ---------------------------------------------------------------------------
__global__ __launch_bounds__(256) void vpack_kernel(
    const float* __restrict__ qkv, unsigned* __restrict__ vth, unsigned* __restrict__ vtl)
{
    int idx = blockIdx.x * blockDim.x + threadIdx.x;
    int s2  = idx & (SS / 2 - 1);
    int hd  = (idx >> 10) & (HDD - 1);
    int kvh = (idx >> 17) & (NKVV - 1);
    int b   = idx >> 19;

    const float* src = qkv + (size_t)(b * SS + 2 * s2) * QKVD
                           + QDIM + KVDIM + kvh * HDD + hd;
    float v0 = src[0], v1 = src[QKVD];
    unsigned hi, lo;
    pack_hilo(v0, v1, hi, lo);
    size_t o = ((size_t)((b * NKVV + kvh) * HDD + hd)) * (SS / 2) + s2;
    vth[o] = hi; vtl[o] = lo;
}

// ---------------------------------------------------------------------------
// Causal flash attention, bf16 mma + ldmatrix, register softmax.
// QK^T: bf16 x3 (full accuracy). PV: P in rn-bf16 (1 plane) x V hi/lo (x2).
// Epilogue writes hi/lo planes for GEMM2 directly (no fp32 intermediate).
// smem (bytes): Qh 0, Ql 34816, K[buf][plane]@69632 (17408 each),
//               Vh 139264, Vl 157696, Ph 176128. total 194560.
// ---------------------------------------------------------------------------
#define ATT_SMEM_BYTES 194560

__global__ __launch_bounds__(256, 1) void attn_bf16_kernel(
    const unsigned* __restrict__ qh, const unsigned* __restrict__ ql,
    const unsigned* __restrict__ kh, const unsigned* __restrict__ kl,
    const unsigned* __restrict__ vth, const unsigned* __restrict__ vtl,
    unsigned* __restrict__ oh, unsigned* __restrict__ ol)
{
    extern __shared__ __align__(16) unsigned char dynsm[];
    unsigned sb = smem_u32(dynsm);

    int tid = threadIdx.x;
    int lane = tid & 31, w = tid >> 5;
    int g = lane >> 2, tc = lane & 3;
    int qt = (SS / 128 - 1) - blockIdx.x;
    int h  = blockIdx.y, b = blockIdx.z;
    int kvh = h >> 2;
    int q0 = qt * 128;
    int ktmax = 2 * qt + 1;
    const float scale = 0.08838834764831845f;

    auto issueK = [&](int kt) {
        if (kt <= ktmax) {
            unsigned dst0 = sb + 69632u + (kt & 1) * 34816u;
            #pragma unroll
            for (int e = 0; e < 8; e++) {
                int i = tid + e * 256;
                int plane = i >> 10, j = i & 1023;
                int r = j >> 4, c = j & 15;
                const unsigned* src = (plane ? kl : kh)
                    + (size_t)(b * SS + kt * 64 + r) * (KVDIM / 2) + kvh * 64 + c * 4;
                cp16u(dst0 + plane * 17408u + r * 272u + c * 16u, src);
            }
        }
        asm volatile("cp.async.commit_group;\n");
    };
    auto issueV = [&](int kt) {
        #pragma unroll
        for (int e = 0; e < 8; e++) {
            int i = tid + e * 256;
            int plane = i >> 10, j = i & 1023;
            int r = j >> 3, c = j & 7;
            const unsigned* src = (plane ? vtl : vth)
                + ((size_t)((b * NKVV + kvh) * HDD + r)) * (SS / 2) + kt * 32 + c * 4;
            cp16u(sb + 139264u + plane * 18432u + r * 144u + c * 16u, src);
        }
        asm volatile("cp.async.commit_group;\n");
    };

    // prologue: [Q + K0] as one group
    {
        #pragma unroll
        for (int e = 0; e < 16; e++) {
            int i = tid + e * 256;
            int plane = i >> 11, j = i & 2047;
            int r = j >> 4, c = j & 15;
            const unsigned* src = (plane ? ql : qh)
                + (size_t)(b * SS + q0 + r) * (QDIM / 2) + h * 64 + c * 4;
            cp16u(sb + plane * 34816u + r * 272u + c * 16u, src);
        }
        unsigned dst0 = sb + 69632u;
        #pragma unroll
        for (int e = 0; e < 8; e++) {
            int i = tid + e * 256;
            int plane = i >> 10, j = i & 1023;
            int r = j >> 4, c = j & 15;
            const unsigned* src = (plane ? kl : kh)
                + (size_t)(b * SS + r) * (KVDIM / 2) + kvh * 64 + c * 4;
            cp16u(dst0 + plane * 17408u + r * 272u + c * 16u, src);
        }
        asm volatile("cp.async.commit_group;\n");
    }

    // fragment address components
    int arow = lane & 15;
    int akc  = (lane >> 4) & 1;
    int brow = (lane & 7) | (((lane >> 4) & 1) << 3);
    int bkc  = (lane >> 3) & 1;

    unsigned aQh = sb + (unsigned)((w * 16 + arow) * 272 + akc * 16);
    unsigned aQl = aQh + 34816u;
    unsigned bKo = (unsigned)(brow * 272 + bkc * 16);
    unsigned aPh = sb + 176128u + (unsigned)((w * 16 + arow) * 144 + akc * 16);
    unsigned bVh = sb + 139264u + (unsigned)(brow * 144 + bkc * 16);

    float m0r = -1e30f, m1r = -1e30f, l0r = 0.f, l1r = 0.f;
    float acc[16][4];
    #pragma unroll
    for (int nf = 0; nf < 16; nf++)
        #pragma unroll
        for (int r = 0; r < 4; r++) acc[nf][r] = 0.f;

    int srow = w * 16 + g;

    for (int kt = 0; kt <= ktmax; kt++) {
        __syncthreads();                 // prev iter done (sV, sK[(kt+1)&1] free)
        issueV(kt);
        issueK(kt + 1);

        asm volatile("cp.async.wait_group 2;\n");   // K[kt] ready
        __syncthreads();

        // warps 0-3 are fully masked in the last iteration (k0 = q0+64 > rows)
        bool active = !(kt == ktmax && w < 4);

        if (active) {
            // ---- S = Q K^T (bf16 x3) ----
            float sacc[8][4] = {};
            unsigned bK = sb + 69632u + (kt & 1) * 34816u + bKo;
            #pragma unroll
            for (int ks = 0; ks < 8; ks++) {
                unsigned qhf[4], qlf[4];
                ldsm4(qhf, aQh + ks * 32);
                ldsm4(qlf, aQl + ks * 32);
                #pragma unroll
                for (int nblk = 0; nblk < 4; nblk++) {
                    unsigned khf[4], klf[4];
                    unsigned ka = bK + nblk * 4352u + ks * 32;
                    ldsm4(khf, ka);
                    ldsm4(klf, ka + 17408u);
                    #pragma unroll
                    for (int sub = 0; sub < 2; sub++) {
                        float* c = sacc[nblk * 2 + sub];
                        const unsigned* bh2 = &khf[sub * 2];
                        const unsigned* bl2 = &klf[sub * 2];
                        mma_bf16(c, qhf, bh2);
                        mma_bf16(c, qhf, bl2);
                        mma_bf16(c, qlf, bh2);
                    }
                }
            }

            // ---- scale + causal mask ----
            {
                int k0 = kt * 64;
                bool diag = (kt >= 2 * qt);
                #pragma unroll
                for (int nf = 0; nf < 8; nf++) {
                    float v0 = sacc[nf][0] * scale, v1 = sacc[nf][1] * scale;
                    float v2 = sacc[nf][2] * scale, v3 = sacc[nf][3] * scale;
                    if (diag) {
                        int qr = q0 + srow, kc = k0 + nf * 8 + 2 * tc;
                        if (kc     > qr)     v0 = -1e30f;
                        if (kc + 1 > qr)     v1 = -1e30f;
                        if (kc     > qr + 8) v2 = -1e30f;
                        if (kc + 1 > qr + 8) v3 = -1e30f;
                    }
                    sacc[nf][0] = v0; sacc[nf][1] = v1;
                    sacc[nf][2] = v2; sacc[nf][3] = v3;
                }
            }

            // ---- register softmax; P packed rn-bf16 (single plane) ----
            float alpha0, alpha1;
            {
                float mx0 = -1e30f, mx1 = -1e30f;
                #pragma unroll
                for (int nf = 0; nf < 8; nf++) {
                    mx0 = fmaxf(mx0, fmaxf(sacc[nf][0], sacc[nf][1]));
                    mx1 = fmaxf(mx1, fmaxf(sacc[nf][2], sacc[nf][3]));
                }
                mx0 = fmaxf(mx0, __shfl_xor_sync(0xffffffffu, mx0, 1));
                mx0 = fmaxf(mx0, __shfl_xor_sync(0xffffffffu, mx0, 2));
                mx1 = fmaxf(mx1, __shfl_xor_sync(0xffffffffu, mx1, 1));
                mx1 = fmaxf(mx1, __shfl_xor_sync(0xffffffffu, mx1, 2));

                float mn0 = fmaxf(m0r, mx0), mn1 = fmaxf(m1r, mx1);
                alpha0 = __expf(m0r - mn0);
                alpha1 = __expf(m1r - mn1);

                unsigned pr0 = sb + 176128u + srow * 144u;
                unsigned pr1 = pr0 + 8 * 144u;
                float s0 = 0.f, s1 = 0.f;
                #pragma unroll
                for (int nf = 0; nf < 8; nf++) {
                    float p0 = __expf(sacc[nf][0] - mn0);
                    float p1 = __expf(sacc[nf][1] - mn0);
                    float p2 = __expf(sacc[nf][2] - mn1);
                    float p3 = __expf(sacc[nf][3] - mn1);
                    s0 += p0 + p1;
                    s1 += p2 + p3;
                    unsigned wo = (nf * 4 + tc) * 4;
                    unsigned pk0 = pack_rn(p0, p1);
                    unsigned pk1 = pack_rn(p2, p3);
                    asm volatile("st.shared.b32 [%0], %1;" :: "r"(pr0 + wo), "r"(pk0));
                    asm volatile("st.shared.b32 [%0], %1;" :: "r"(pr1 + wo), "r"(pk1));
                }
                s0 += __shfl_xor_sync(0xffffffffu, s0, 1);
                s0 += __shfl_xor_sync(0xffffffffu, s0, 2);
                s1 += __shfl_xor_sync(0xffffffffu, s1, 1);
                s1 += __shfl_xor_sync(0xffffffffu, s1, 2);
                l0r = l0r * alpha0 + s0;
                l1r = l1r * alpha1 + s1;
                m0r = mn0; m1r = mn1;
            }
            __syncwarp();

            // ---- rescale O ----
            #pragma unroll
            for (int nf = 0; nf < 16; nf++) {
                acc[nf][0] *= alpha0; acc[nf][1] *= alpha0;
                acc[nf][2] *= alpha1; acc[nf][3] *= alpha1;
            }
        }

        asm volatile("cp.async.wait_group 1;\n");   // V[kt] ready
        __syncthreads();

        if (active) {
            // ---- O += P V (P x (Vh + Vl)) ----
            #pragma unroll
            for (int ks = 0; ks < 4; ks++) {
                unsigned phf[4];
                ldsm4(phf, aPh + ks * 32);
                #pragma unroll
                for (int nblk = 0; nblk < 8; nblk++) {
                    unsigned vhf[4], vlf[4];
                    unsigned va = bVh + nblk * 2304u + ks * 32;
                    ldsm4(vhf, va);
                    ldsm4(vlf, va + 18432u);
                    #pragma unroll
                    for (int sub = 0; sub < 2; sub++) {
                        float* c = acc[nblk * 2 + sub];
                        mma_bf16(c, phf, &vhf[sub * 2]);
                        mma_bf16(c, phf, &vlf[sub * 2]);
                    }
                }
            }
        }
    }

    // ---- epilogue: write hi/lo planes directly (GEMM2 A operand) ----
    float inv0 = 1.f / l0r;
    float inv1 = 1.f / l1r;
    int row = q0 + srow;
    size_t o0 = (size_t)(b * SS + row) * (QDIM / 2) + h * 64;
    size_t o1 = o0 + (size_t)8 * (QDIM / 2);
    #pragma unroll
    for (int nf = 0; nf < 16; nf++) {
        unsigned hi, lo;
        pack_hilo(acc[nf][0] * inv0, acc[nf][1] * inv0, hi, lo);
        oh[o0 + nf * 4 + tc] = hi;
        ol[o0 + nf * 4 + tc] = lo;
        pack_hilo(acc[nf][2] * inv1, acc[nf][3] * inv1, hi, lo);
        oh[o1 + nf * 4 + tc] = hi;
        ol[o1 + nf * 4 + tc] = lo;
    }
}

// ---------------------------------------------------------------------------
extern "C" void kernel_launch(void* const* d_in, const int* in_sizes, int n_in,
                              void* d_out, int out_size)
{
    (void)in_sizes; (void)n_in; (void)out_size;
    const float* x     = (const float*)d_in[0];
    const float* freqs = (const float*)d_in[1];
    const float* Wqkv  = (const float*)d_in[2];
    const float* Wo    = (const float*)d_in[3];
    float* out = (float*)d_out;

    float *qkvp;
    unsigned *xh, *xl, *wqh, *wql, *ah, *al, *woh, *wol;
    unsigned *qh, *ql, *kh, *kl, *vth, *vtl;
    cudaGetSymbolAddress((void**)&qkvp, g_qkv);
    cudaGetSymbolAddress((void**)&xh, g_xh);   cudaGetSymbolAddress((void**)&xl, g_xl);
    cudaGetSymbolAddress((void**)&wqh, g_wqh); cudaGetSymbolAddress((void**)&wql, g_wql);
    cudaGetSymbolAddress((void**)&ah, g_ah);   cudaGetSymbolAddress((void**)&al, g_al);
    cudaGetSymbolAddress((void**)&woh, g_woh); cudaGetSymbolAddress((void**)&wol, g_wol);
    cudaGetSymbolAddress((void**)&qh, g_qh);   cudaGetSymbolAddress((void**)&ql, g_ql);
    cudaGetSymbolAddress((void**)&kh, g_kh);   cudaGetSymbolAddress((void**)&kl, g_kl);
    cudaGetSymbolAddress((void**)&vth, g_vth); cudaGetSymbolAddress((void**)&vtl, g_vtl);

    cudaFuncSetAttribute(attn_bf16_kernel, cudaFuncAttributeMaxDynamicSharedMemorySize,
                         ATT_SMEM_BYTES);
    cudaFuncSetAttribute(gemm_planes_nt, cudaFuncAttributeMaxDynamicSharedMemorySize,
                         GEMM_SMEM_BYTES);

    // 0) split inputs into bf16 hi/lo planes
    {
        int n4;
        n4 = MROWS * DD / 4;
        split_kernel<<<n4 / 256, 256>>>((const float4*)x, (uint2*)xh, (uint2*)xl, n4);
        n4 = QKVD * DD / 4;
        split_kernel<<<n4 / 256, 256>>>((const float4*)Wqkv, (uint2*)wqh, (uint2*)wql, n4);
        n4 = DD * QDIM / 4;
        split_kernel<<<n4 / 256, 256>>>((const float4*)Wo, (uint2*)woh, (uint2*)wol, n4);
    }

    // 1) QKV projection (bf16x3, ldmatrix)
    gemm_planes_nt<<<dim3(QKVD / 128, MROWS / 128), 256, GEMM_SMEM_BYTES>>>(
        xh, xl, wqh, wql, qkvp, MROWS, QKVD, DD);

    // 2) RoPE -> q/k bf16 planes; V transpose+pack
    rope_qk_kernel<<<(BB * SS * 20 * 64) / 256, 256>>>(qkvp, freqs, qh, ql, kh, kl);
    vpack_kernel<<<(BB * NKVV * HDD * (SS / 2)) / 256, 256>>>(qkvp, vth, vtl);

    // 3) causal GQA flash attention -> hi/lo planes directly
    attn_bf16_kernel<<<dim3(SS / 128, NHH, BB), 256, ATT_SMEM_BYTES>>>(
        qh, ql, kh, kl, vth, vtl, ah, al);

    // 4) output projection (bf16x3, ldmatrix)
    gemm_planes_nt<<<dim3(DD / 128, MROWS / 128), 256, GEMM_SMEM_BYTES>>>(
        ah, al, woh, wol, out, MROWS, DD, QDIM);
}

// round 11
// speedup vs baseline: 1.0527x; 1.0023x over previous
#include <cuda_runtime.h>
#include <cuda_fp16.h>

#define BB 2
#define SS 2048
#define DD 2048
#define NHH 16
#define NKVV 4
#define HDD 128
#define QDIM 2048
#define KVDIM 512
#define QKVD 3072
#define MROWS (BB*SS)   // 4096

// fp32 scratch
__device__ float g_qkv[(size_t)MROWS * QKVD];

// packed bf16 hi/lo planes for projections (one u32 = 2 adjacent-k bf16)
__device__ unsigned g_xh[(size_t)MROWS * DD / 2],   g_xl[(size_t)MROWS * DD / 2];
__device__ unsigned g_wqh[(size_t)QKVD * DD / 2],   g_wql[(size_t)QKVD * DD / 2];
__device__ unsigned g_ah[(size_t)MROWS * QDIM / 2], g_al[(size_t)MROWS * QDIM / 2];
__device__ unsigned g_woh[(size_t)DD * QDIM / 2],   g_wol[(size_t)DD * QDIM / 2];

// attention operand planes (q/k bf16 hi/lo; v f16 hi/lo)
__device__ unsigned g_qh[(size_t)MROWS * QDIM / 2],  g_ql[(size_t)MROWS * QDIM / 2];
__device__ unsigned g_kh[(size_t)MROWS * KVDIM / 2], g_kl[(size_t)MROWS * KVDIM / 2];
__device__ unsigned g_vth[(size_t)BB * NKVV * HDD * SS / 2],
                    g_vtl[(size_t)BB * NKVV * HDD * SS / 2];

// ---------------------------------------------------------------------------
// helpers
// ---------------------------------------------------------------------------
__device__ __forceinline__ void mma_bf16(float* c, const unsigned* a, const unsigned* b) {
    asm volatile(
        "mma.sync.aligned.m16n8k16.row.col.f32.bf16.bf16.f32 "
        "{%0,%1,%2,%3},{%4,%5,%6,%7},{%8,%9},{%0,%1,%2,%3};"
        : "+f"(c[0]), "+f"(c[1]), "+f"(c[2]), "+f"(c[3])
        : "r"(a[0]), "r"(a[1]), "r"(a[2]), "r"(a[3]), "r"(b[0]), "r"(b[1]));
}

__device__ __forceinline__ void mma_f16(float* c, const unsigned* a, const unsigned* b) {
    asm volatile(
        "mma.sync.aligned.m16n8k16.row.col.f32.f16.f16.f32 "
        "{%0,%1,%2,%3},{%4,%5,%6,%7},{%8,%9},{%0,%1,%2,%3};"
        : "+f"(c[0]), "+f"(c[1]), "+f"(c[2]), "+f"(c[3])
        : "r"(a[0]), "r"(a[1]), "r"(a[2]), "r"(a[3]), "r"(b[0]), "r"(b[1]));
}

__device__ __forceinline__ void ldsm4(unsigned* r, unsigned addr) {
    asm volatile("ldmatrix.sync.aligned.m8n8.x4.shared.b16 {%0,%1,%2,%3}, [%4];"
                 : "=r"(r[0]), "=r"(r[1]), "=r"(r[2]), "=r"(r[3]) : "r"(addr));
}

__device__ __forceinline__ void cp16u(unsigned smem_dst, const void* gsrc) {
    asm volatile("cp.async.ca.shared.global [%0], [%1], 16;\n" :: "r"(smem_dst), "l"(gsrc));
}

__device__ __forceinline__ unsigned smem_u32(const void* p) {
    return (unsigned)__cvta_generic_to_shared(p);
}

// pack two fp32 (even, odd) into bf16 hi word + lo word (even -> low half)
__device__ __forceinline__ void pack_hilo(float p0, float p1, unsigned& hi, unsigned& lo) {
    unsigned u0 = __float_as_uint(p0), u1 = __float_as_uint(p1);
    asm("prmt.b32 %0, %1, %2, 0x7632;" : "=r"(hi) : "r"(u0), "r"(u1));
    float l0 = p0 - __uint_as_float(u0 & 0xffff0000u);
    float l1 = p1 - __uint_as_float(u1 & 0xffff0000u);
    asm("cvt.rn.satfinite.bf16x2.f32 %0, %1, %2;" : "=r"(lo) : "f"(l1), "f"(l0));
}

// pack two fp32 into f16 hi word + f16 lo (residual) word (even -> low half)
__device__ __forceinline__ void pack_hilo_f16(float v0, float v1, unsigned& hi, unsigned& lo) {
    __half h0 = __float2half_rn(v0);
    __half h1 = __float2half_rn(v1);
    __half2 hh = __halves2half2(h0, h1);
    hi = *(unsigned*)&hh;
    __half2 ll = __halves2half2(__float2half_rn(v0 - __half2float(h0)),
                                __float2half_rn(v1 - __half2float(h1)));
    lo = *(unsigned*)&ll;
}

__device__ __forceinline__ unsigned pack_rn_f16(float p0, float p1) {
    __half2 hh = __halves2half2(__float2half_rn(p0), __float2half_rn(p1));
    return *(unsigned*)&hh;
}

// ---------------------------------------------------------------------------
// Split fp32 -> packed bf16 hi/lo planes
// ---------------------------------------------------------------------------
__global__ __launch_bounds__(256) void split_kernel(
    const float4* __restrict__ in, uint2* __restrict__ hi, uint2* __restrict__ lo,
    int n4)
{
    int i = blockIdx.x * blockDim.x + threadIdx.x;
    if (i >= n4) return;
    float4 v = in[i];
    uint2 h, l;
    pack_hilo(v.x, v.y, h.x, l.x);
    pack_hilo(v.z, v.w, h.y, l.y);
    hi[i] = h;
    lo[i] = l;
}

// ---------------------------------------------------------------------------
// Pure-bf16 x3 NT GEMM on pre-split planes, ldmatrix fragment loads.
// (unchanged — at legacy-HMMA ceiling)
// ---------------------------------------------------------------------------
#define PLANE_W (128 * 20)
#define STAGE_W (4 * PLANE_W)
#define GEMM_SMEM_BYTES (2 * STAGE_W * 4)
#define PLANE_B (PLANE_W * 4)
#define STAGE_B (STAGE_W * 4)

__global__ __launch_bounds__(256, 2) void gemm_planes_nt(
    const unsigned* __restrict__ Ah, const unsigned* __restrict__ Al,
    const unsigned* __restrict__ Bh, const unsigned* __restrict__ Bl,
    float* __restrict__ C, int M, int N, int K)
{
    extern __shared__ unsigned usm[];
    const int KW = K >> 1;

    int tid = threadIdx.x;
    int lane = tid & 31, w = tid >> 5;
    int wm = w >> 2, wn = w & 3;
    int g = lane >> 2, tc = lane & 3;
    int m0 = blockIdx.y * 128, n0 = blockIdx.x * 128;

    int lr = tid >> 2;
    int lw = (tid & 3) * 4;

    const unsigned* gp[4] = {
        Ah + (size_t)(m0 + lr) * KW + lw,
        Al + (size_t)(m0 + lr) * KW + lw,
        Bh + (size_t)(n0 + lr) * KW + lw,
        Bl + (size_t)(n0 + lr) * KW + lw };

    float acc[4][4][4] = {};

    auto load_stage = [&](int t, int buf) {
        unsigned* st = usm + buf * STAGE_W;
        size_t ko = (size_t)t * 16;
        #pragma unroll
        for (int p = 0; p < 4; p++) {
            #pragma unroll
            for (int r2 = 0; r2 < 2; r2++) {
                unsigned* d = st + p * PLANE_W + (lr + r2 * 64) * 20 + lw;
                cp16u((unsigned)__cvta_generic_to_shared(d),
                      gp[p] + (size_t)r2 * 64 * KW + ko);
            }
        }
        asm volatile("cp.async.commit_group;\n");
    };

    unsigned smem_base = smem_u32(usm);
    int arow = lane & 15;
    int akc  = (lane >> 4) & 1;
    int brow = (lane & 7) | (((lane >> 4) & 1) << 3);
    int bkc  = (lane >> 3) & 1;

    unsigned aH = smem_base + 0 * PLANE_B + (unsigned)((wm * 64 + arow) * 80 + akc * 16);
    unsigned aL = aH + PLANE_B;
    unsigned bH = smem_base + 2 * PLANE_B + (unsigned)((wn * 32 + brow) * 80 + bkc * 16);
    unsigned bL = bH + PLANE_B;

    int T = K / 32;
    load_stage(0, 0);

    for (int t = 0; t < T; t++) {
        asm volatile("cp.async.wait_group 0;\n");
        __syncthreads();
        if (t + 1 < T) load_stage(t + 1, (t + 1) & 1);

        unsigned stg = (t & 1) * STAGE_B;

        #pragma unroll
        for (int ks = 0; ks < 2; ks++) {
            unsigned ah[4][4], al[4][4], bhp[2][4], blp[2][4];
            unsigned kso = stg + ks * 32;
            #pragma unroll
            for (int mf = 0; mf < 4; mf++) {
                ldsm4(ah[mf], aH + kso + mf * 1280);
                ldsm4(al[mf], aL + kso + mf * 1280);
            }
            #pragma unroll
            for (int p = 0; p < 2; p++) {
                ldsm4(bhp[p], bH + kso + p * 1280);
                ldsm4(blp[p], bL + kso + p * 1280);
            }
            #pragma unroll
            for (int mf = 0; mf < 4; mf++)
                #pragma unroll
                for (int nf = 0; nf < 4; nf++) {
                    const unsigned* bhf = &bhp[nf >> 1][(nf & 1) * 2];
                    const unsigned* blf = &blp[nf >> 1][(nf & 1) * 2];
                    mma_bf16(acc[mf][nf], ah[mf], bhf);
                    mma_bf16(acc[mf][nf], ah[mf], blf);
                    mma_bf16(acc[mf][nf], al[mf], bhf);
                }
        }
        __syncthreads();
    }

    #pragma unroll
    for (int mf = 0; mf < 4; mf++) {
        #pragma unroll
        for (int nf = 0; nf < 4; nf++) {
            int row = m0 + wm * 64 + mf * 16 + g;
            int col = n0 + wn * 32 + nf * 8 + 2 * tc;
            *(float2*)(C + (size_t)row * N + col) =
                make_float2(acc[mf][nf][0], acc[mf][nf][1]);
            *(float2*)(C + (size_t)(row + 8) * N + col) =
                make_float2(acc[mf][nf][2], acc[mf][nf][3]);
        }
    }
}

// ---------------------------------------------------------------------------
// RoPE on q,k -> packed bf16 hi/lo planes.
// ---------------------------------------------------------------------------
__global__ __launch_bounds__(256) void rope_qk_kernel(
    const float* __restrict__ qkv, const float* __restrict__ freqs,
    unsigned* __restrict__ qh, unsigned* __restrict__ ql,
    unsigned* __restrict__ kh, unsigned* __restrict__ kl)
{
    int idx = blockIdx.x * blockDim.x + threadIdx.x;
    int i    = idx & 63;
    int head = (idx >> 6) % 20;
    int bs   = idx / (64 * 20);
    int s    = bs & (SS - 1);

    int off = (head < NHH) ? head * HDD : QDIM + (head - NHH) * HDD;
    size_t base = (size_t)bs * QKVD + off + 2 * i;
    float t0 = qkv[base], t1 = qkv[base + 1];
    float f0 = freqs[s * HDD + 2 * i];
    float f1 = freqs[s * HDD + 2 * i + 1];
    float r0 = t0 * f1 - t1 * f0;
    float r1 = t0 * f0 + t1 * f1;
    unsigned hi, lo;
    pack_hilo(r0, r1, hi, lo);
    if (head < NHH) {
        size_t o = (size_t)bs * (QDIM / 2) + head * 64 + i;
        qh[o] = hi; ql[o] = lo;
    } else {
        size_t o = (size_t)bs * (KVDIM / 2) + (head - NHH) * 64 + i;
        kh[o] = hi; kl[o] = lo;
    }
}

// ---------------------------------------------------------------------------
// V pack + transpose -> f16 hi/lo planes, vt[b][kvh][hd][s].
// ---------------------------------------------------------------------------
__global__ __launch_bounds__(256) void vpack_kernel(
    const float* __restrict__ qkv, unsigned* __restrict__ vth, unsigned* __restrict__ vtl)
{
    int idx = blockIdx.x * blockDim.x + threadIdx.x;
    int s2  = idx & (SS / 2 - 1);
    int hd  = (idx >> 10) & (HDD - 1);
    int kvh = (idx >> 17) & (NKVV - 1);
    int b   = idx >> 19;

    const float* src = qkv + (size_t)(b * SS + 2 * s2) * QKVD
                           + QDIM + KVDIM + kvh * HDD + hd;
    float v0 = src[0], v1 = src[QKVD];
    unsigned hi, lo;
    pack_hilo_f16(v0, v1, hi, lo);
    size_t o = ((size_t)((b * NKVV + kvh) * HDD + hd)) * (SS / 2) + s2;
    vth[o] = hi; vtl[o] = lo;
}

// ---------------------------------------------------------------------------
// Causal flash attention. QK^T: bf16 x3. PV: P rn-f16 x V f16 hi/lo.
// Single block-barrier per iteration: K AND V double-buffered; K/V for
// iteration kt+1 issued as ONE cp.async group right after the barrier
// (overwrites buffers last read in iter kt-1, released by this barrier).
// smem (bytes): Qh 0, Ql 34816, K[buf][plane]@69632 (17408 each, buf 34816),
//               V[buf][plane]@139264 (18432 each, buf 36864), P@212992.
// total 231424.
// ---------------------------------------------------------------------------
#define ATT_SMEM_BYTES 231424

__global__ __launch_bounds__(256, 1) void attn_bf16_kernel(
    const unsigned* __restrict__ qh, const unsigned* __restrict__ ql,
    const unsigned* __restrict__ kh, const unsigned* __restrict__ kl,
    const unsigned* __restrict__ vth, const unsigned* __restrict__ vtl,
    unsigned* __restrict__ oh, unsigned* __restrict__ ol)
{
    extern __shared__ __align__(16) unsigned char dynsm[];
    unsigned sb = smem_u32(dynsm);

    int tid = threadIdx.x;
    int lane = tid & 31, w = tid >> 5;
    int g = lane >> 2, tc = lane & 3;
    int qt = (SS / 128 - 1) - blockIdx.x;
    int h  = blockIdx.y, b = blockIdx.z;
    int kvh = h >> 2;
    int q0 = qt * 128;
    int ktmax = 2 * qt + 1;
    const float scale = 0.08838834764831845f;

    auto loadK = [&](int kt) {
        unsigned dst0 = sb + 69632u + (kt & 1) * 34816u;
        #pragma unroll
        for (int e = 0; e < 8; e++) {
            int i = tid + e * 256;
            int plane = i >> 10, j = i & 1023;
            int r = j >> 4, c = j & 15;
            const unsigned* src = (plane ? kl : kh)
                + (size_t)(b * SS + kt * 64 + r) * (KVDIM / 2) + kvh * 64 + c * 4;
            cp16u(dst0 + plane * 17408u + r * 272u + c * 16u, src);
        }
    };
    auto loadV = [&](int kt) {
        unsigned dst0 = sb + 139264u + (kt & 1) * 36864u;
        #pragma unroll
        for (int e = 0; e < 8; e++) {
            int i = tid + e * 256;
            int plane = i >> 10, j = i & 1023;
            int r = j >> 3, c = j & 7;
            const unsigned* src = (plane ? vtl : vth)
                + ((size_t)((b * NKVV + kvh) * HDD + r)) * (SS / 2) + kt * 32 + c * 4;
            cp16u(dst0 + plane * 18432u + r * 144u + c * 16u, src);
        }
    };

    // prologue: [Q + K0 + V0] as one group
    {
        #pragma unroll
        for (int e = 0; e < 16; e++) {
            int i = tid + e * 256;
            int plane = i >> 11, j = i & 2047;
            int r = j >> 4, c = j & 15;
            const unsigned* src = (plane ? ql : qh)
                + (size_t)(b * SS + q0 + r) * (QDIM / 2) + h * 64 + c * 4;
            cp16u(sb + plane * 34816u + r * 272u + c * 16u, src);
        }
        loadK(0);
        loadV(0);
        asm volatile("cp.async.commit_group;\n");
    }

    // fragment address components
    int arow = lane & 15;
    int akc  = (lane >> 4) & 1;
    int brow = (lane & 7) | (((lane >> 4) & 1) << 3);
    int bkc  = (lane >> 3) & 1;

    unsigned aQh = sb + (unsigned)((w * 16 + arow) * 272 + akc * 16);
    unsigned aQl = aQh + 34816u;
    unsigned bKo = (unsigned)(brow * 272 + bkc * 16);
    unsigned bVo = (unsigned)(brow * 144 + bkc * 16);
    unsigned aPh = sb + 212992u + (unsigned)((w * 16 + arow) * 144 + akc * 16);

    float m0r = -1e30f, m1r = -1e30f, l0r = 0.f, l1r = 0.f;
    float acc[16][4];
    #pragma unroll
    for (int nf = 0; nf < 16; nf++)
        #pragma unroll
        for (int r = 0; r < 4; r++) acc[nf][r] = 0.f;

    int srow = w * 16 + g;

    for (int kt = 0; kt <= ktmax; kt++) {
        asm volatile("cp.async.wait_group 0;\n");   // K[kt],V[kt] arrived
        __syncthreads();                 // all warps done iter kt-1 -> buffers free

        if (kt + 1 <= ktmax) {           // issue next K+V (consumed next iter)
            loadK(kt + 1);
            loadV(kt + 1);
            asm volatile("cp.async.commit_group;\n");
        }

        // warps 0-3 fully masked in the last iteration (k0 = q0+64 > their rows)
        bool active = !(kt == ktmax && w < 4);
        if (!active) continue;

        // ---- S = Q K^T (bf16 x3) ----
        float sacc[8][4] = {};
        unsigned bK = sb + 69632u + (kt & 1) * 34816u + bKo;
        #pragma unroll
        for (int ks = 0; ks < 8; ks++) {
            unsigned qhf[4], qlf[4];
            ldsm4(qhf, aQh + ks * 32);
            ldsm4(qlf, aQl + ks * 32);
            #pragma unroll
            for (int nblk = 0; nblk < 4; nblk++) {
                unsigned khf[4], klf[4];
                unsigned ka = bK + nblk * 4352u + ks * 32;
                ldsm4(khf, ka);
                ldsm4(klf, ka + 17408u);
                #pragma unroll
                for (int sub = 0; sub < 2; sub++) {
                    float* c = sacc[nblk * 2 + sub];
                    const unsigned* bh2 = &khf[sub * 2];
                    const unsigned* bl2 = &klf[sub * 2];
                    mma_bf16(c, qhf, bh2);
                    mma_bf16(c, qhf, bl2);
                    mma_bf16(c, qlf, bh2);
                }
            }
        }

        // ---- scale + causal mask ----
        {
            int k0 = kt * 64;
            bool diag = (kt >= 2 * qt);
            #pragma unroll
            for (int nf = 0; nf < 8; nf++) {
                float v0 = sacc[nf][0] * scale, v1 = sacc[nf][1] * scale;
                float v2 = sacc[nf][2] * scale, v3 = sacc[nf][3] * scale;
                if (diag) {
                    int qr = q0 + srow, kc = k0 + nf * 8 + 2 * tc;
                    if (kc     > qr)     v0 = -1e30f;
                    if (kc + 1 > qr)     v1 = -1e30f;
                    if (kc     > qr + 8) v2 = -1e30f;
                    if (kc + 1 > qr + 8) v3 = -1e30f;
                }
                sacc[nf][0] = v0; sacc[nf][1] = v1;
                sacc[nf][2] = v2; sacc[nf][3] = v3;
            }
        }

        // ---- register softmax; P packed rn-f16 (single plane) ----
        float alpha0, alpha1;
        {
            float mx0 = -1e30f, mx1 = -1e30f;
            #pragma unroll
            for (int nf = 0; nf < 8; nf++) {
                mx0 = fmaxf(mx0, fmaxf(sacc[nf][0], sacc[nf][1]));
                mx1 = fmaxf(mx1, fmaxf(sacc[nf][2], sacc[nf][3]));
            }
            mx0 = fmaxf(mx0, __shfl_xor_sync(0xffffffffu, mx0, 1));
            mx0 = fmaxf(mx0, __shfl_xor_sync(0xffffffffu, mx0, 2));
            mx1 = fmaxf(mx1, __shfl_xor_sync(0xffffffffu, mx1, 1));
            mx1 = fmaxf(mx1, __shfl_xor_sync(0xffffffffu, mx1, 2));

            float mn0 = fmaxf(m0r, mx0), mn1 = fmaxf(m1r, mx1);
            alpha0 = __expf(m0r - mn0);
            alpha1 = __expf(m1r - mn1);

            unsigned pr0 = sb + 212992u + srow * 144u;
            unsigned pr1 = pr0 + 8 * 144u;
            float s0 = 0.f, s1 = 0.f;
            #pragma unroll
            for (int nf = 0; nf < 8; nf++) {
                float p0 = __expf(sacc[nf][0] - mn0);
                float p1 = __expf(sacc[nf][1] - mn0);
                float p2 = __expf(sacc[nf][2] - mn1);
                float p3 = __expf(sacc[nf][3] - mn1);
                s0 += p0 + p1;
                s1 += p2 + p3;
                unsigned wo = (nf * 4 + tc) * 4;
                unsigned pk0 = pack_rn_f16(p0, p1);
                unsigned pk1 = pack_rn_f16(p2, p3);
                asm volatile("st.shared.b32 [%0], %1;" :: "r"(pr0 + wo), "r"(pk0));
                asm volatile("st.shared.b32 [%0], %1;" :: "r"(pr1 + wo), "r"(pk1));
            }
            s0 += __shfl_xor_sync(0xffffffffu, s0, 1);
            s0 += __shfl_xor_sync(0xffffffffu, s0, 2);
            s1 += __shfl_xor_sync(0xffffffffu, s1, 1);
            s1 += __shfl_xor_sync(0xffffffffu, s1, 2);
            l0r = l0r * alpha0 + s0;
            l1r = l1r * alpha1 + s1;
            m0r = mn0; m1r = mn1;
        }
        __syncwarp();                    // P warp-private

        // ---- rescale O ----
        #pragma unroll
        for (int nf = 0; nf < 16; nf++) {
            acc[nf][0] *= alpha0; acc[nf][1] *= alpha0;
            acc[nf][2] *= alpha1; acc[nf][3] *= alpha1;
        }

        // ---- O += P V (f16: P x (Vh + Vl)) ----
        unsigned bV = sb + 139264u + (kt & 1) * 36864u + bVo;
        #pragma unroll
        for (int ks = 0; ks < 4; ks++) {
            unsigned phf[4];
            ldsm4(phf, aPh + ks * 32);
            #pragma unroll
            for (int nblk = 0; nblk < 8; nblk++) {
                unsigned vhf[4], vlf[4];
                unsigned va = bV + nblk * 2304u + ks * 32;
                ldsm4(vhf, va);
                ldsm4(vlf, va + 18432u);
                #pragma unroll
                for (int sub = 0; sub < 2; sub++) {
                    float* c = acc[nblk * 2 + sub];
                    mma_f16(c, phf, &vhf[sub * 2]);
                    mma_f16(c, phf, &vlf[sub * 2]);
                }
            }
        }
    }

    // ---- epilogue: write bf16 hi/lo planes directly (GEMM2 A operand) ----
    float inv0 = 1.f / l0r;
    float inv1 = 1.f / l1r;
    int row = q0 + srow;
    size_t o0 = (size_t)(b * SS + row) * (QDIM / 2) + h * 64;
    size_t o1 = o0 + (size_t)8 * (QDIM / 2);
    #pragma unroll
    for (int nf = 0; nf < 16; nf++) {
        unsigned hi, lo;
        pack_hilo(acc[nf][0] * inv0, acc[nf][1] * inv0, hi, lo);
        oh[o0 + nf * 4 + tc] = hi;
        ol[o0 + nf * 4 + tc] = lo;
        pack_hilo(acc[nf][2] * inv1, acc[nf][3] * inv1, hi, lo);
        oh[o1 + nf * 4 + tc] = hi;
        ol[o1 + nf * 4 + tc] = lo;
    }
}

// ---------------------------------------------------------------------------
extern "C" void kernel_launch(void* const* d_in, const int* in_sizes, int n_in,
                              void* d_out, int out_size)
{
    (void)in_sizes; (void)n_in; (void)out_size;
    const float* x     = (const float*)d_in[0];
    const float* freqs = (const float*)d_in[1];
    const float* Wqkv  = (const float*)d_in[2];
    const float* Wo    = (const float*)d_in[3];
    float* out = (float*)d_out;

    float *qkvp;
    unsigned *xh, *xl, *wqh, *wql, *ah, *al, *woh, *wol;
    unsigned *qh, *ql, *kh, *kl, *vth, *vtl;
    cudaGetSymbolAddress((void**)&qkvp, g_qkv);
    cudaGetSymbolAddress((void**)&xh, g_xh);   cudaGetSymbolAddress((void**)&xl, g_xl);
    cudaGetSymbolAddress((void**)&wqh, g_wqh); cudaGetSymbolAddress((void**)&wql, g_wql);
    cudaGetSymbolAddress((void**)&ah, g_ah);   cudaGetSymbolAddress((void**)&al, g_al);
    cudaGetSymbolAddress((void**)&woh, g_woh); cudaGetSymbolAddress((void**)&wol, g_wol);
    cudaGetSymbolAddress((void**)&qh, g_qh);   cudaGetSymbolAddress((void**)&ql, g_ql);
    cudaGetSymbolAddress((void**)&kh, g_kh);   cudaGetSymbolAddress((void**)&kl, g_kl);
    cudaGetSymbolAddress((void**)&vth, g_vth); cudaGetSymbolAddress((void**)&vtl, g_vtl);

    cudaFuncSetAttribute(attn_bf16_kernel, cudaFuncAttributeMaxDynamicSharedMemorySize,
                         ATT_SMEM_BYTES);
    cudaFuncSetAttribute(gemm_planes_nt, cudaFuncAttributeMaxDynamicSharedMemorySize,
                         GEMM_SMEM_BYTES);

    // 0) split inputs into bf16 hi/lo planes
    {
        int n4;
        n4 = MROWS * DD / 4;
        split_kernel<<<n4 / 256, 256>>>((const float4*)x, (uint2*)xh, (uint2*)xl, n4);
        n4 = QKVD * DD / 4;
        split_kernel<<<n4 / 256, 256>>>((const float4*)Wqkv, (uint2*)wqh, (uint2*)wql, n4);
        n4 = DD * QDIM / 4;
        split_kernel<<<n4 / 256, 256>>>((const float4*)Wo, (uint2*)woh, (uint2*)wol, n4);
    }

    // 1) QKV projection (bf16x3, ldmatrix)
    gemm_planes_nt<<<dim3(QKVD / 128, MROWS / 128), 256, GEMM_SMEM_BYTES>>>(
        xh, xl, wqh, wql, qkvp, MROWS, QKVD, DD);

    // 2) RoPE -> q/k bf16 planes; V transpose+pack (f16)
    rope_qk_kernel<<<(BB * SS * 20 * 64) / 256, 256>>>(qkvp, freqs, qh, ql, kh, kl);
    vpack_kernel<<<(BB * NKVV * HDD * (SS / 2)) / 256, 256>>>(qkvp, vth, vtl);

    // 3) causal GQA flash attention -> hi/lo planes directly
    attn_bf16_kernel<<<dim3(SS / 128, NHH, BB), 256, ATT_SMEM_BYTES>>>(
        qh, ql, kh, kl, vth, vtl, ah, al);

    // 4) output projection (bf16x3, ldmatrix)
    gemm_planes_nt<<<dim3(DD / 128, MROWS / 128), 256, GEMM_SMEM_BYTES>>>(
        ah, al, woh, wol, out, MROWS, DD, QDIM);
}

// round 12
// speedup vs baseline: 1.1494x; 1.0919x over previous
#include <cuda_runtime.h>
#include <cuda_fp16.h>

#define BB 2
#define SS 2048
#define DD 2048
#define NHH 16
#define NKVV 4
#define HDD 128
#define QDIM 2048
#define KVDIM 512
#define QKVD 3072
#define MROWS (BB*SS)   // 4096

// scale/sqrt(hd) * log2(e): Q pre-scaled so S emerges in log2 domain
#define SCALE_L2E (0.08838834764831845f * 1.44269504088896340f)

// fp32 scratch
__device__ float g_qkv[(size_t)MROWS * QKVD];

// packed bf16 hi/lo planes for projections
__device__ unsigned g_xh[(size_t)MROWS * DD / 2],   g_xl[(size_t)MROWS * DD / 2];
__device__ unsigned g_wqh[(size_t)QKVD * DD / 2],   g_wql[(size_t)QKVD * DD / 2];
__device__ unsigned g_ah[(size_t)MROWS * QDIM / 2], g_al[(size_t)MROWS * QDIM / 2];
__device__ unsigned g_woh[(size_t)DD * QDIM / 2],   g_wol[(size_t)DD * QDIM / 2];

// attention operand planes (q/k bf16 hi/lo; v single f16 plane)
__device__ unsigned g_qh[(size_t)MROWS * QDIM / 2],  g_ql[(size_t)MROWS * QDIM / 2];
__device__ unsigned g_kh[(size_t)MROWS * KVDIM / 2], g_kl[(size_t)MROWS * KVDIM / 2];
__device__ unsigned g_vth[(size_t)BB * NKVV * HDD * SS / 2];

// ---------------------------------------------------------------------------
// helpers
// ---------------------------------------------------------------------------
__device__ __forceinline__ void mma_bf16(float* c, const unsigned* a, const unsigned* b) {
    asm volatile(
        "mma.sync.aligned.m16n8k16.row.col.f32.bf16.bf16.f32 "
        "{%0,%1,%2,%3},{%4,%5,%6,%7},{%8,%9},{%0,%1,%2,%3};"
        : "+f"(c[0]), "+f"(c[1]), "+f"(c[2]), "+f"(c[3])
        : "r"(a[0]), "r"(a[1]), "r"(a[2]), "r"(a[3]), "r"(b[0]), "r"(b[1]));
}

__device__ __forceinline__ void mma_f16(float* c, const unsigned* a, const unsigned* b) {
    asm volatile(
        "mma.sync.aligned.m16n8k16.row.col.f32.f16.f16.f32 "
        "{%0,%1,%2,%3},{%4,%5,%6,%7},{%8,%9},{%0,%1,%2,%3};"
        : "+f"(c[0]), "+f"(c[1]), "+f"(c[2]), "+f"(c[3])
        : "r"(a[0]), "r"(a[1]), "r"(a[2]), "r"(a[3]), "r"(b[0]), "r"(b[1]));
}

__device__ __forceinline__ void ldsm4(unsigned* r, unsigned addr) {
    asm volatile("ldmatrix.sync.aligned.m8n8.x4.shared.b16 {%0,%1,%2,%3}, [%4];"
                 : "=r"(r[0]), "=r"(r[1]), "=r"(r[2]), "=r"(r[3]) : "r"(addr));
}

__device__ __forceinline__ void cp16u(unsigned smem_dst, const void* gsrc) {
    asm volatile("cp.async.ca.shared.global [%0], [%1], 16;\n" :: "r"(smem_dst), "l"(gsrc));
}

__device__ __forceinline__ unsigned smem_u32(const void* p) {
    return (unsigned)__cvta_generic_to_shared(p);
}

__device__ __forceinline__ void pack_hilo(float p0, float p1, unsigned& hi, unsigned& lo) {
    unsigned u0 = __float_as_uint(p0), u1 = __float_as_uint(p1);
    asm("prmt.b32 %0, %1, %2, 0x7632;" : "=r"(hi) : "r"(u0), "r"(u1));
    float l0 = p0 - __uint_as_float(u0 & 0xffff0000u);
    float l1 = p1 - __uint_as_float(u1 & 0xffff0000u);
    asm("cvt.rn.satfinite.bf16x2.f32 %0, %1, %2;" : "=r"(lo) : "f"(l1), "f"(l0));
}

__device__ __forceinline__ unsigned pack_rn_f16(float p0, float p1) {
    unsigned r;
    asm("cvt.rn.f16x2.f32 %0, %1, %2;" : "=r"(r) : "f"(p1), "f"(p0));
    return r;
}

__device__ __forceinline__ float ex2f(float x) {
    float r;
    asm("ex2.approx.f32 %0, %1;" : "=f"(r) : "f"(x));
    return r;
}

// 2 exps in one MUFU op: d = 2^(packed f16x2)
__device__ __forceinline__ unsigned ex2_f16x2(unsigned x) {
    unsigned r;
    asm("ex2.approx.f16x2 %0, %1;" : "=r"(r) : "r"(x));
    return r;
}

// ---------------------------------------------------------------------------
// Split fp32 -> packed bf16 hi/lo planes
// ---------------------------------------------------------------------------
__global__ __launch_bounds__(256) void split_kernel(
    const float4* __restrict__ in, uint2* __restrict__ hi, uint2* __restrict__ lo,
    int n4)
{
    int i = blockIdx.x * blockDim.x + threadIdx.x;
    if (i >= n4) return;
    float4 v = in[i];
    uint2 h, l;
    pack_hilo(v.x, v.y, h.x, l.x);
    pack_hilo(v.z, v.w, h.y, l.y);
    hi[i] = h;
    lo[i] = l;
}

// ---------------------------------------------------------------------------
// Pure-bf16 x3 NT GEMM on pre-split planes, ldmatrix fragment loads.
// (unchanged — at legacy-HMMA ceiling)
// ---------------------------------------------------------------------------
#define PLANE_W (128 * 20)
#define STAGE_W (4 * PLANE_W)
#define GEMM_SMEM_BYTES (2 * STAGE_W * 4)
#define PLANE_B (PLANE_W * 4)
#define STAGE_B (STAGE_W * 4)

__global__ __launch_bounds__(256, 2) void gemm_planes_nt(
    const unsigned* __restrict__ Ah, const unsigned* __restrict__ Al,
    const unsigned* __restrict__ Bh, const unsigned* __restrict__ Bl,
    float* __restrict__ C, int M, int N, int K)
{
    extern __shared__ unsigned usm[];
    const int KW = K >> 1;

    int tid = threadIdx.x;
    int lane = tid & 31, w = tid >> 5;
    int wm = w >> 2, wn = w & 3;
    int g = lane >> 2, tc = lane & 3;
    int m0 = blockIdx.y * 128, n0 = blockIdx.x * 128;

    int lr = tid >> 2;
    int lw = (tid & 3) * 4;

    const unsigned* gp[4] = {
        Ah + (size_t)(m0 + lr) * KW + lw,
        Al + (size_t)(m0 + lr) * KW + lw,
        Bh + (size_t)(n0 + lr) * KW + lw,
        Bl + (size_t)(n0 + lr) * KW + lw };

    float acc[4][4][4] = {};

    auto load_stage = [&](int t, int buf) {
        unsigned* st = usm + buf * STAGE_W;
        size_t ko = (size_t)t * 16;
        #pragma unroll
        for (int p = 0; p < 4; p++) {
            #pragma unroll
            for (int r2 = 0; r2 < 2; r2++) {
                unsigned* d = st + p * PLANE_W + (lr + r2 * 64) * 20 + lw;
                cp16u((unsigned)__cvta_generic_to_shared(d),
                      gp[p] + (size_t)r2 * 64 * KW + ko);
            }
        }
        asm volatile("cp.async.commit_group;\n");
    };

    unsigned smem_base = smem_u32(usm);
    int arow = lane & 15;
    int akc  = (lane >> 4) & 1;
    int brow = (lane & 7) | (((lane >> 4) & 1) << 3);
    int bkc  = (lane >> 3) & 1;

    unsigned aH = smem_base + 0 * PLANE_B + (unsigned)((wm * 64 + arow) * 80 + akc * 16);
    unsigned aL = aH + PLANE_B;
    unsigned bH = smem_base + 2 * PLANE_B + (unsigned)((wn * 32 + brow) * 80 + bkc * 16);
    unsigned bL = bH + PLANE_B;

    int T = K / 32;
    load_stage(0, 0);

    for (int t = 0; t < T; t++) {
        asm volatile("cp.async.wait_group 0;\n");
        __syncthreads();
        if (t + 1 < T) load_stage(t + 1, (t + 1) & 1);

        unsigned stg = (t & 1) * STAGE_B;

        #pragma unroll
        for (int ks = 0; ks < 2; ks++) {
            unsigned ah[4][4], al[4][4], bhp[2][4], blp[2][4];
            unsigned kso = stg + ks * 32;
            #pragma unroll
            for (int mf = 0; mf < 4; mf++) {
                ldsm4(ah[mf], aH + kso + mf * 1280);
                ldsm4(al[mf], aL + kso + mf * 1280);
            }
            #pragma unroll
            for (int p = 0; p < 2; p++) {
                ldsm4(bhp[p], bH + kso + p * 1280);
                ldsm4(blp[p], bL + kso + p * 1280);
            }
            #pragma unroll
            for (int mf = 0; mf < 4; mf++)
                #pragma unroll
                for (int nf = 0; nf < 4; nf++) {
                    const unsigned* bhf = &bhp[nf >> 1][(nf & 1) * 2];
                    const unsigned* blf = &blp[nf >> 1][(nf & 1) * 2];
                    mma_bf16(acc[mf][nf], ah[mf], bhf);
                    mma_bf16(acc[mf][nf], ah[mf], blf);
                    mma_bf16(acc[mf][nf], al[mf], bhf);
                }
        }
        __syncthreads();
    }

    #pragma unroll
    for (int mf = 0; mf < 4; mf++) {
        #pragma unroll
        for (int nf = 0; nf < 4; nf++) {
            int row = m0 + wm * 64 + mf * 16 + g;
            int col = n0 + wn * 32 + nf * 8 + 2 * tc;
            *(float2*)(C + (size_t)row * N + col) =
                make_float2(acc[mf][nf][0], acc[mf][nf][1]);
            *(float2*)(C + (size_t)(row + 8) * N + col) =
                make_float2(acc[mf][nf][2], acc[mf][nf][3]);
        }
    }
}

// ---------------------------------------------------------------------------
// RoPE on q,k -> packed bf16 hi/lo planes. Q pre-scaled by scale*log2e.
// ---------------------------------------------------------------------------
__global__ __launch_bounds__(256) void rope_qk_kernel(
    const float* __restrict__ qkv, const float* __restrict__ freqs,
    unsigned* __restrict__ qh, unsigned* __restrict__ ql,
    unsigned* __restrict__ kh, unsigned* __restrict__ kl)
{
    int idx = blockIdx.x * blockDim.x + threadIdx.x;
    int i    = idx & 63;
    int head = (idx >> 6) % 20;
    int bs   = idx / (64 * 20);
    int s    = bs & (SS - 1);

    int off = (head < NHH) ? head * HDD : QDIM + (head - NHH) * HDD;
    size_t base = (size_t)bs * QKVD + off + 2 * i;
    float t0 = qkv[base], t1 = qkv[base + 1];
    float f0 = freqs[s * HDD + 2 * i];
    float f1 = freqs[s * HDD + 2 * i + 1];
    float r0 = t0 * f1 - t1 * f0;
    float r1 = t0 * f0 + t1 * f1;
    unsigned hi, lo;
    if (head < NHH) {
        pack_hilo(r0 * SCALE_L2E, r1 * SCALE_L2E, hi, lo);
        size_t o = (size_t)bs * (QDIM / 2) + head * 64 + i;
        qh[o] = hi; ql[o] = lo;
    } else {
        pack_hilo(r0, r1, hi, lo);
        size_t o = (size_t)bs * (KVDIM / 2) + (head - NHH) * 64 + i;
        kh[o] = hi; kl[o] = lo;
    }
}

// ---------------------------------------------------------------------------
// V pack + transpose -> single f16 plane, vt[b][kvh][hd][s].
// ---------------------------------------------------------------------------
__global__ __launch_bounds__(256) void vpack_kernel(
    const float* __restrict__ qkv, unsigned* __restrict__ vth)
{
    int idx = blockIdx.x * blockDim.x + threadIdx.x;
    int s2  = idx & (SS / 2 - 1);
    int hd  = (idx >> 10) & (HDD - 1);
    int kvh = (idx >> 17) & (NKVV - 1);
    int b   = idx >> 19;

    const float* src = qkv + (size_t)(b * SS + 2 * s2) * QKVD
                           + QDIM + KVDIM + kvh * HDD + hd;
    size_t o = ((size_t)((b * NKVV + kvh) * HDD + hd)) * (SS / 2) + s2;
    vth[o] = pack_rn_f16(src[0], src[QKVD]);
}

// ---------------------------------------------------------------------------
// Causal flash attention. QK^T: bf16 x3 (log2-domain, scale folded into Q).
// Softmax: ex2.approx.f16x2 (2 exps / MUFU op); row-sum l via ones-B mma.
// PV: P f16 x V f16 (single planes).
// smem (bytes): Qh 0 (34816), Ql 34816, K@69632 2bufs x 2planes x 17408,
//               V@139264 2 bufs x 18432, P@176128 (18432). total 194560.
// ---------------------------------------------------------------------------
#define ATT_SMEM_BYTES 194560

__global__ __launch_bounds__(256, 1) void attn_bf16_kernel(
    const unsigned* __restrict__ qh, const unsigned* __restrict__ ql,
    const unsigned* __restrict__ kh, const unsigned* __restrict__ kl,
    const unsigned* __restrict__ vth,
    unsigned* __restrict__ oh, unsigned* __restrict__ ol)
{
    extern __shared__ __align__(16) unsigned char dynsm[];
    unsigned sb = smem_u32(dynsm);

    int tid = threadIdx.x;
    int lane = tid & 31, w = tid >> 5;
    int g = lane >> 2, tc = lane & 3;
    int qt = (SS / 128 - 1) - blockIdx.x;
    int h  = blockIdx.y, b = blockIdx.z;
    int kvh = h >> 2;
    int q0 = qt * 128;
    int ktmax = 2 * qt + 1;

    auto loadK = [&](int kt) {
        unsigned dst0 = sb + 69632u + (kt & 1) * 34816u;
        #pragma unroll
        for (int e = 0; e < 8; e++) {
            int i = tid + e * 256;
            int plane = i >> 10, j = i & 1023;
            int r = j >> 4, c = j & 15;
            const unsigned* src = (plane ? kl : kh)
                + (size_t)(b * SS + kt * 64 + r) * (KVDIM / 2) + kvh * 64 + c * 4;
            cp16u(dst0 + plane * 17408u + r * 272u + c * 16u, src);
        }
    };
    auto loadV = [&](int kt) {
        unsigned dst0 = sb + 139264u + (kt & 1) * 18432u;
        #pragma unroll
        for (int e = 0; e < 4; e++) {
            int i = tid + e * 256;
            int r = i >> 3, c = i & 7;
            const unsigned* src = vth
                + ((size_t)((b * NKVV + kvh) * HDD + r)) * (SS / 2) + kt * 32 + c * 4;
            cp16u(dst0 + r * 144u + c * 16u, src);
        }
    };

    // prologue: [Q + K0 + V0] as one group
    {
        #pragma unroll
        for (int e = 0; e < 16; e++) {
            int i = tid + e * 256;
            int plane = i >> 11, j = i & 2047;
            int r = j >> 4, c = j & 15;
            const unsigned* src = (plane ? ql : qh)
                + (size_t)(b * SS + q0 + r) * (QDIM / 2) + h * 64 + c * 4;
            cp16u(sb + plane * 34816u + r * 272u + c * 16u, src);
        }
        loadK(0);
        loadV(0);
        asm volatile("cp.async.commit_group;\n");
    }

    // fragment address components
    int arow = lane & 15;
    int akc  = (lane >> 4) & 1;
    int brow = (lane & 7) | (((lane >> 4) & 1) << 3);
    int bkc  = (lane >> 3) & 1;

    unsigned aQh = sb + (unsigned)((w * 16 + arow) * 272 + akc * 16);
    unsigned aQl = aQh + 34816u;
    unsigned bKo = (unsigned)(brow * 272 + bkc * 16);
    unsigned bVo = (unsigned)(brow * 144 + bkc * 16);
    unsigned aPh = sb + 176128u + (unsigned)((w * 16 + arow) * 144 + akc * 16);

    const unsigned onesf[2] = { 0x3C003C00u, 0x3C003C00u };  // f16 {1,1},{1,1}

    float m0r = -1e30f, m1r = -1e30f;
    float lacc[4] = {};                  // rows srow/srow+8 sums (via ones-mma)
    float acc[16][4];
    #pragma unroll
    for (int nf = 0; nf < 16; nf++)
        #pragma unroll
        for (int r = 0; r < 4; r++) acc[nf][r] = 0.f;

    int srow = w * 16 + g;

    for (int kt = 0; kt <= ktmax; kt++) {
        asm volatile("cp.async.wait_group 0;\n");   // K[kt],V[kt] arrived
        __syncthreads();                 // all warps done iter kt-1 -> buffers free

        if (kt + 1 <= ktmax) {
            loadK(kt + 1);
            loadV(kt + 1);
            asm volatile("cp.async.commit_group;\n");
        }

        bool active = !(kt == ktmax && w < 4);
        if (!active) continue;

        // ---- S = Q K^T (bf16 x3; result already in log2 domain) ----
        float sacc[8][4] = {};
        unsigned bK = sb + 69632u + (kt & 1) * 34816u + bKo;
        #pragma unroll
        for (int ks = 0; ks < 8; ks++) {
            unsigned qhf[4], qlf[4];
            ldsm4(qhf, aQh + ks * 32);
            ldsm4(qlf, aQl + ks * 32);
            #pragma unroll
            for (int nblk = 0; nblk < 4; nblk++) {
                unsigned khf[4], klf[4];
                unsigned ka = bK + nblk * 4352u + ks * 32;
                ldsm4(khf, ka);
                ldsm4(klf, ka + 17408u);
                #pragma unroll
                for (int sub = 0; sub < 2; sub++) {
                    float* c = sacc[nblk * 2 + sub];
                    const unsigned* bh2 = &khf[sub * 2];
                    const unsigned* bl2 = &klf[sub * 2];
                    mma_bf16(c, qhf, bh2);
                    mma_bf16(c, qhf, bl2);
                    mma_bf16(c, qlf, bh2);
                }
            }
        }

        // ---- causal mask (scale already folded into Q) ----
        if (kt >= 2 * qt) {
            int k0 = kt * 64;
            #pragma unroll
            for (int nf = 0; nf < 8; nf++) {
                int qr = q0 + srow, kc = k0 + nf * 8 + 2 * tc;
                if (kc     > qr)     sacc[nf][0] = -1e30f;
                if (kc + 1 > qr)     sacc[nf][1] = -1e30f;
                if (kc     > qr + 8) sacc[nf][2] = -1e30f;
                if (kc + 1 > qr + 8) sacc[nf][3] = -1e30f;
            }
        }

        // ---- register softmax: p = 2^(s-m) via ex2.approx.f16x2 ----
        float alpha0, alpha1;
        {
            float mx0 = -1e30f, mx1 = -1e30f;
            #pragma unroll
            for (int nf = 0; nf < 8; nf++) {
                mx0 = fmaxf(mx0, fmaxf(sacc[nf][0], sacc[nf][1]));
                mx1 = fmaxf(mx1, fmaxf(sacc[nf][2], sacc[nf][3]));
            }
            mx0 = fmaxf(mx0, __shfl_xor_sync(0xffffffffu, mx0, 1));
            mx0 = fmaxf(mx0, __shfl_xor_sync(0xffffffffu, mx0, 2));
            mx1 = fmaxf(mx1, __shfl_xor_sync(0xffffffffu, mx1, 1));
            mx1 = fmaxf(mx1, __shfl_xor_sync(0xffffffffu, mx1, 2));

            float mn0 = fmaxf(m0r, mx0), mn1 = fmaxf(m1r, mx1);
            alpha0 = ex2f(m0r - mn0);
            alpha1 = ex2f(m1r - mn1);
            m0r = mn0; m1r = mn1;

            unsigned pr0 = sb + 176128u + srow * 144u;
            unsigned pr1 = pr0 + 8 * 144u;
            #pragma unroll
            for (int nf = 0; nf < 8; nf++) {
                unsigned t0 = pack_rn_f16(sacc[nf][0] - mn0, sacc[nf][1] - mn0);
                unsigned t1 = pack_rn_f16(sacc[nf][2] - mn1, sacc[nf][3] - mn1);
                unsigned pk0 = ex2_f16x2(t0);
                unsigned pk1 = ex2_f16x2(t1);
                unsigned wo = (nf * 4 + tc) * 4;
                asm volatile("st.shared.b32 [%0], %1;" :: "r"(pr0 + wo), "r"(pk0));
                asm volatile("st.shared.b32 [%0], %1;" :: "r"(pr1 + wo), "r"(pk1));
            }
        }
        __syncwarp();                    // P warp-private

        // ---- rescale O and l ----
        #pragma unroll
        for (int nf = 0; nf < 16; nf++) {
            acc[nf][0] *= alpha0; acc[nf][1] *= alpha0;
            acc[nf][2] *= alpha1; acc[nf][3] *= alpha1;
        }
        lacc[0] *= alpha0; lacc[1] *= alpha0;
        lacc[2] *= alpha1; lacc[3] *= alpha1;

        // ---- O += P V ; l += P·1 (ones-mma) ----
        unsigned bV = sb + 139264u + (kt & 1) * 18432u + bVo;
        #pragma unroll
        for (int ks = 0; ks < 4; ks++) {
            unsigned phf[4];
            ldsm4(phf, aPh + ks * 32);
            mma_f16(lacc, phf, onesf);
            #pragma unroll
            for (int nblk = 0; nblk < 8; nblk++) {
                unsigned vhf[4];
                ldsm4(vhf, bV + nblk * 2304u + ks * 32);
                mma_f16(acc[nblk * 2 + 0], phf, &vhf[0]);
                mma_f16(acc[nblk * 2 + 1], phf, &vhf[2]);
            }
        }
    }

    // ---- epilogue: write bf16 hi/lo planes directly (GEMM2 A operand) ----
    float inv0 = 1.f / lacc[0];
    float inv1 = 1.f / lacc[2];
    int row = q0 + srow;
    size_t o0 = (size_t)(b * SS + row) * (QDIM / 2) + h * 64;
    size_t o1 = o0 + (size_t)8 * (QDIM / 2);
    #pragma unroll
    for (int nf = 0; nf < 16; nf++) {
        unsigned hi, lo;
        pack_hilo(acc[nf][0] * inv0, acc[nf][1] * inv0, hi, lo);
        oh[o0 + nf * 4 + tc] = hi;
        ol[o0 + nf * 4 + tc] = lo;
        pack_hilo(acc[nf][2] * inv1, acc[nf][3] * inv1, hi, lo);
        oh[o1 + nf * 4 + tc] = hi;
        ol[o1 + nf * 4 + tc] = lo;
    }
}

// ---------------------------------------------------------------------------
extern "C" void kernel_launch(void* const* d_in, const int* in_sizes, int n_in,
                              void* d_out, int out_size)
{
    (void)in_sizes; (void)n_in; (void)out_size;
    const float* x     = (const float*)d_in[0];
    const float* freqs = (const float*)d_in[1];
    const float* Wqkv  = (const float*)d_in[2];
    const float* Wo    = (const float*)d_in[3];
    float* out = (float*)d_out;

    float *qkvp;
    unsigned *xh, *xl, *wqh, *wql, *ah, *al, *woh, *wol;
    unsigned *qh, *ql, *kh, *kl, *vth;
    cudaGetSymbolAddress((void**)&qkvp, g_qkv);
    cudaGetSymbolAddress((void**)&xh, g_xh);   cudaGetSymbolAddress((void**)&xl, g_xl);
    cudaGetSymbolAddress((void**)&wqh, g_wqh); cudaGetSymbolAddress((void**)&wql, g_wql);
    cudaGetSymbolAddress((void**)&ah, g_ah);   cudaGetSymbolAddress((void**)&al, g_al);
    cudaGetSymbolAddress((void**)&woh, g_woh); cudaGetSymbolAddress((void**)&wol, g_wol);
    cudaGetSymbolAddress((void**)&qh, g_qh);   cudaGetSymbolAddress((void**)&ql, g_ql);
    cudaGetSymbolAddress((void**)&kh, g_kh);   cudaGetSymbolAddress((void**)&kl, g_kl);
    cudaGetSymbolAddress((void**)&vth, g_vth);

    cudaFuncSetAttribute(attn_bf16_kernel, cudaFuncAttributeMaxDynamicSharedMemorySize,
                         ATT_SMEM_BYTES);
    cudaFuncSetAttribute(gemm_planes_nt, cudaFuncAttributeMaxDynamicSharedMemorySize,
                         GEMM_SMEM_BYTES);

    // 0) split inputs into bf16 hi/lo planes
    {
        int n4;
        n4 = MROWS * DD / 4;
        split_kernel<<<n4 / 256, 256>>>((const float4*)x, (uint2*)xh, (uint2*)xl, n4);
        n4 = QKVD * DD / 4;
        split_kernel<<<n4 / 256, 256>>>((const float4*)Wqkv, (uint2*)wqh, (uint2*)wql, n4);
        n4 = DD * QDIM / 4;
        split_kernel<<<n4 / 256, 256>>>((const float4*)Wo, (uint2*)woh, (uint2*)wol, n4);
    }

    // 1) QKV projection (bf16x3, ldmatrix)
    gemm_planes_nt<<<dim3(QKVD / 128, MROWS / 128), 256, GEMM_SMEM_BYTES>>>(
        xh, xl, wqh, wql, qkvp, MROWS, QKVD, DD);

    // 2) RoPE -> q/k bf16 planes (q pre-scaled to log2 domain); V pack (f16)
    rope_qk_kernel<<<(BB * SS * 20 * 64) / 256, 256>>>(qkvp, freqs, qh, ql, kh, kl);
    vpack_kernel<<<(BB * NKVV * HDD * (SS / 2)) / 256, 256>>>(qkvp, vth);

    // 3) causal GQA flash attention -> hi/lo planes directly
    attn_bf16_kernel<<<dim3(SS / 128, NHH, BB), 256, ATT_SMEM_BYTES>>>(
        qh, ql, kh, kl, vth, ah, al);

    // 4) output projection (bf16x3, ldmatrix)
    gemm_planes_nt<<<dim3(DD / 128, MROWS / 128), 256, GEMM_SMEM_BYTES>>>(
        ah, al, woh, wol, out, MROWS, DD, QDIM);
}

// round 14
// speedup vs baseline: 1.2258x; 1.0665x over previous
#include <cuda_runtime.h>
#include <cuda_fp16.h>

#define BB 2
#define SS 2048
#define DD 2048
#define NHH 16
#define NKVV 4
#define HDD 128
#define QDIM 2048
#define KVDIM 512
#define QKVD 3072
#define MROWS (BB*SS)   // 4096

#define SCALE_L2E (0.08838834764831845f * 1.44269504088896340f)

// fp32 scratch
__device__ float g_qkv[(size_t)MROWS * QKVD];

// packed bf16 hi/lo planes for projections
__device__ unsigned g_xh[(size_t)MROWS * DD / 2],   g_xl[(size_t)MROWS * DD / 2];
__device__ unsigned g_wqh[(size_t)QKVD * DD / 2],   g_wql[(size_t)QKVD * DD / 2];
__device__ unsigned g_ah[(size_t)MROWS * QDIM / 2], g_al[(size_t)MROWS * QDIM / 2];
__device__ unsigned g_woh[(size_t)DD * QDIM / 2],   g_wol[(size_t)DD * QDIM / 2];

// attention operand planes (q/k/v all single f16 planes)
__device__ unsigned g_qh[(size_t)MROWS * QDIM / 2];
__device__ unsigned g_kh[(size_t)MROWS * KVDIM / 2];
__device__ unsigned g_vth[(size_t)BB * NKVV * HDD * SS / 2];

// ---------------------------------------------------------------------------
// helpers
// ---------------------------------------------------------------------------
__device__ __forceinline__ void mma_bf16(float* c, const unsigned* a, const unsigned* b) {
    asm volatile(
        "mma.sync.aligned.m16n8k16.row.col.f32.bf16.bf16.f32 "
        "{%0,%1,%2,%3},{%4,%5,%6,%7},{%8,%9},{%0,%1,%2,%3};"
        : "+f"(c[0]), "+f"(c[1]), "+f"(c[2]), "+f"(c[3])
        : "r"(a[0]), "r"(a[1]), "r"(a[2]), "r"(a[3]), "r"(b[0]), "r"(b[1]));
}

__device__ __forceinline__ void mma_f16(float* c, const unsigned* a, const unsigned* b) {
    asm volatile(
        "mma.sync.aligned.m16n8k16.row.col.f32.f16.f16.f32 "
        "{%0,%1,%2,%3},{%4,%5,%6,%7},{%8,%9},{%0,%1,%2,%3};"
        : "+f"(c[0]), "+f"(c[1]), "+f"(c[2]), "+f"(c[3])
        : "r"(a[0]), "r"(a[1]), "r"(a[2]), "r"(a[3]), "r"(b[0]), "r"(b[1]));
}

__device__ __forceinline__ void ldsm4(unsigned* r, unsigned addr) {
    asm volatile("ldmatrix.sync.aligned.m8n8.x4.shared.b16 {%0,%1,%2,%3}, [%4];"
                 : "=r"(r[0]), "=r"(r[1]), "=r"(r[2]), "=r"(r[3]) : "r"(addr));
}

__device__ __forceinline__ void cp16u(unsigned smem_dst, const void* gsrc) {
    asm volatile("cp.async.ca.shared.global [%0], [%1], 16;\n" :: "r"(smem_dst), "l"(gsrc));
}

__device__ __forceinline__ unsigned smem_u32(const void* p) {
    return (unsigned)__cvta_generic_to_shared(p);
}

__device__ __forceinline__ void pack_hilo(float p0, float p1, unsigned& hi, unsigned& lo) {
    unsigned u0 = __float_as_uint(p0), u1 = __float_as_uint(p1);
    asm("prmt.b32 %0, %1, %2, 0x7632;" : "=r"(hi) : "r"(u0), "r"(u1));
    float l0 = p0 - __uint_as_float(u0 & 0xffff0000u);
    float l1 = p1 - __uint_as_float(u1 & 0xffff0000u);
    asm("cvt.rn.satfinite.bf16x2.f32 %0, %1, %2;" : "=r"(lo) : "f"(l1), "f"(l0));
}

__device__ __forceinline__ unsigned pack_rn_f16(float p0, float p1) {
    unsigned r;
    asm("cvt.rn.f16x2.f32 %0, %1, %2;" : "=r"(r) : "f"(p1), "f"(p0));
    return r;
}

__device__ __forceinline__ float ex2f(float x) {
    float r;
    asm("ex2.approx.f32 %0, %1;" : "=f"(r) : "f"(x));
    return r;
}

__device__ __forceinline__ unsigned ex2_f16x2(unsigned x) {
    unsigned r;
    asm("ex2.approx.f16x2 %0, %1;" : "=r"(r) : "r"(x));
    return r;
}

// ---------------------------------------------------------------------------
// Split fp32 -> packed bf16 hi/lo planes
// ---------------------------------------------------------------------------
__global__ __launch_bounds__(256) void split_kernel(
    const float4* __restrict__ in, uint2* __restrict__ hi, uint2* __restrict__ lo,
    int n4)
{
    int i = blockIdx.x * blockDim.x + threadIdx.x;
    if (i >= n4) return;
    float4 v = in[i];
    uint2 h, l;
    pack_hilo(v.x, v.y, h.x, l.x);
    pack_hilo(v.z, v.w, h.y, l.y);
    hi[i] = h;
    lo[i] = l;
}

// ---------------------------------------------------------------------------
// Pure-bf16 x3 NT GEMM on pre-split planes (unchanged — at HMMA ceiling)
// ---------------------------------------------------------------------------
#define PLANE_W (128 * 20)
#define STAGE_W (4 * PLANE_W)
#define GEMM_SMEM_BYTES (2 * STAGE_W * 4)
#define PLANE_B (PLANE_W * 4)
#define STAGE_B (STAGE_W * 4)

__global__ __launch_bounds__(256, 2) void gemm_planes_nt(
    const unsigned* __restrict__ Ah, const unsigned* __restrict__ Al,
    const unsigned* __restrict__ Bh, const unsigned* __restrict__ Bl,
    float* __restrict__ C, int M, int N, int K)
{
    extern __shared__ unsigned usm[];
    const int KW = K >> 1;

    int tid = threadIdx.x;
    int lane = tid & 31, w = tid >> 5;
    int wm = w >> 2, wn = w & 3;
    int g = lane >> 2, tc = lane & 3;
    int m0 = blockIdx.y * 128, n0 = blockIdx.x * 128;

    int lr = tid >> 2;
    int lw = (tid & 3) * 4;

    const unsigned* gp[4] = {
        Ah + (size_t)(m0 + lr) * KW + lw,
        Al + (size_t)(m0 + lr) * KW + lw,
        Bh + (size_t)(n0 + lr) * KW + lw,
        Bl + (size_t)(n0 + lr) * KW + lw };

    float acc[4][4][4] = {};

    auto load_stage = [&](int t, int buf) {
        unsigned* st = usm + buf * STAGE_W;
        size_t ko = (size_t)t * 16;
        #pragma unroll
        for (int p = 0; p < 4; p++) {
            #pragma unroll
            for (int r2 = 0; r2 < 2; r2++) {
                unsigned* d = st + p * PLANE_W + (lr + r2 * 64) * 20 + lw;
                cp16u((unsigned)__cvta_generic_to_shared(d),
                      gp[p] + (size_t)r2 * 64 * KW + ko);
            }
        }
        asm volatile("cp.async.commit_group;\n");
    };

    unsigned smem_base = smem_u32(usm);
    int arow = lane & 15;
    int akc  = (lane >> 4) & 1;
    int brow = (lane & 7) | (((lane >> 4) & 1) << 3);
    int bkc  = (lane >> 3) & 1;

    unsigned aH = smem_base + 0 * PLANE_B + (unsigned)((wm * 64 + arow) * 80 + akc * 16);
    unsigned aL = aH + PLANE_B;
    unsigned bH = smem_base + 2 * PLANE_B + (unsigned)((wn * 32 + brow) * 80 + bkc * 16);
    unsigned bL = bH + PLANE_B;

    int T = K / 32;
    load_stage(0, 0);

    for (int t = 0; t < T; t++) {
        asm volatile("cp.async.wait_group 0;\n");
        __syncthreads();
        if (t + 1 < T) load_stage(t + 1, (t + 1) & 1);

        unsigned stg = (t & 1) * STAGE_B;

        #pragma unroll
        for (int ks = 0; ks < 2; ks++) {
            unsigned ah[4][4], al[4][4], bhp[2][4], blp[2][4];
            unsigned kso = stg + ks * 32;
            #pragma unroll
            for (int mf = 0; mf < 4; mf++) {
                ldsm4(ah[mf], aH + kso + mf * 1280);
                ldsm4(al[mf], aL + kso + mf * 1280);
            }
            #pragma unroll
            for (int p = 0; p < 2; p++) {
                ldsm4(bhp[p], bH + kso + p * 1280);
                ldsm4(blp[p], bL + kso + p * 1280);
            }
            #pragma unroll
            for (int mf = 0; mf < 4; mf++)
                #pragma unroll
                for (int nf = 0; nf < 4; nf++) {
                    const unsigned* bhf = &bhp[nf >> 1][(nf & 1) * 2];
                    const unsigned* blf = &blp[nf >> 1][(nf & 1) * 2];
                    mma_bf16(acc[mf][nf], ah[mf], bhf);
                    mma_bf16(acc[mf][nf], ah[mf], blf);
                    mma_bf16(acc[mf][nf], al[mf], bhf);
                }
        }
        __syncthreads();
    }

    #pragma unroll
    for (int mf = 0; mf < 4; mf++) {
        #pragma unroll
        for (int nf = 0; nf < 4; nf++) {
            int row = m0 + wm * 64 + mf * 16 + g;
            int col = n0 + wn * 32 + nf * 8 + 2 * tc;
            *(float2*)(C + (size_t)row * N + col) =
                make_float2(acc[mf][nf][0], acc[mf][nf][1]);
            *(float2*)(C + (size_t)(row + 8) * N + col) =
                make_float2(acc[mf][nf][2], acc[mf][nf][3]);
        }
    }
}

// ---------------------------------------------------------------------------
// RoPE on q,k -> single f16 planes. Q pre-scaled by scale*log2e.
// ---------------------------------------------------------------------------
__global__ __launch_bounds__(256) void rope_qk_kernel(
    const float* __restrict__ qkv, const float* __restrict__ freqs,
    unsigned* __restrict__ qh, unsigned* __restrict__ kh)
{
    int idx = blockIdx.x * blockDim.x + threadIdx.x;
    int i    = idx & 63;
    int head = (idx >> 6) % 20;
    int bs   = idx / (64 * 20);
    int s    = bs & (SS - 1);

    int off = (head < NHH) ? head * HDD : QDIM + (head - NHH) * HDD;
    size_t base = (size_t)bs * QKVD + off + 2 * i;
    float t0 = qkv[base], t1 = qkv[base + 1];
    float f0 = freqs[s * HDD + 2 * i];
    float f1 = freqs[s * HDD + 2 * i + 1];
    float r0 = t0 * f1 - t1 * f0;
    float r1 = t0 * f0 + t1 * f1;
    if (head < NHH) {
        size_t o = (size_t)bs * (QDIM / 2) + head * 64 + i;
        qh[o] = pack_rn_f16(r0 * SCALE_L2E, r1 * SCALE_L2E);
    } else {
        size_t o = (size_t)bs * (KVDIM / 2) + (head - NHH) * 64 + i;
        kh[o] = pack_rn_f16(r0, r1);
    }
}

// ---------------------------------------------------------------------------
// V pack + transpose -> single f16 plane, vt[b][kvh][hd][s].
// ---------------------------------------------------------------------------
__global__ __launch_bounds__(256) void vpack_kernel(
    const float* __restrict__ qkv, unsigned* __restrict__ vth)
{
    int idx = blockIdx.x * blockDim.x + threadIdx.x;
    int s2  = idx & (SS / 2 - 1);
    int hd  = (idx >> 10) & (HDD - 1);
    int kvh = (idx >> 17) & (NKVV - 1);
    int b   = idx >> 19;

    const float* src = qkv + (size_t)(b * SS + 2 * s2) * QKVD
                           + QDIM + KVDIM + kvh * HDD + hd;
    size_t o = ((size_t)((b * NKVV + kvh) * HDD + hd)) * (SS / 2) + s2;
    vth[o] = pack_rn_f16(src[0], src[QKVD]);
}

// ---------------------------------------------------------------------------
// Causal flash attention, all-f16 mma. QK^T: single-plane f16 (log2 domain).
// Softmax: ex2.approx.f16x2; l via ones-B mma. PV: f16 x f16.
// smem (bytes): Q @0 (34816), K @34816 (2 bufs x 17408), V @69632 (18432),
//               P @88064 (18432). total 106496 -> 2 CTAs/SM.
// ---------------------------------------------------------------------------
#define ATT_SMEM_BYTES 106496

__global__ __launch_bounds__(256, 2) void attn_f16_kernel(
    const unsigned* __restrict__ qh, const unsigned* __restrict__ kh,
    const unsigned* __restrict__ vth,
    unsigned* __restrict__ oh, unsigned* __restrict__ ol)
{
    extern __shared__ __align__(16) unsigned char dynsm[];
    unsigned sb = smem_u32(dynsm);

    int tid = threadIdx.x;
    int lane = tid & 31, w = tid >> 5;
    int g = lane >> 2, tc = lane & 3;
    int qt = (SS / 128 - 1) - blockIdx.x;
    int h  = blockIdx.y, b = blockIdx.z;
    int kvh = h >> 2;
    int q0 = qt * 128;
    int ktmax = 2 * qt + 1;

    auto loadK = [&](int kt) {
        unsigned dst0 = sb + 34816u + (kt & 1) * 17408u;
        #pragma unroll
        for (int e = 0; e < 4; e++) {
            int i = tid + e * 256;
            int r = i >> 4, c = i & 15;
            const unsigned* src = kh
                + (size_t)(b * SS + kt * 64 + r) * (KVDIM / 2) + kvh * 64 + c * 4;
            cp16u(dst0 + r * 272u + c * 16u, src);
        }
    };
    auto loadV = [&](int kt) {
        unsigned dst0 = sb + 69632u;
        #pragma unroll
        for (int e = 0; e < 4; e++) {
            int i = tid + e * 256;
            int r = i >> 3, c = i & 7;
            const unsigned* src = vth
                + ((size_t)((b * NKVV + kvh) * HDD + r)) * (SS / 2) + kt * 32 + c * 4;
            cp16u(dst0 + r * 144u + c * 16u, src);
        }
    };

    // prologue: [Q + K0] as one group
    {
        #pragma unroll
        for (int e = 0; e < 8; e++) {
            int i = tid + e * 256;
            int r = i >> 4, c = i & 15;
            const unsigned* src = qh
                + (size_t)(b * SS + q0 + r) * (QDIM / 2) + h * 64 + c * 4;
            cp16u(sb + r * 272u + c * 16u, src);
        }
        loadK(0);
        asm volatile("cp.async.commit_group;\n");
    }

    // fragment address components
    int arow = lane & 15;
    int akc  = (lane >> 4) & 1;
    int brow = (lane & 7) | (((lane >> 4) & 1) << 3);
    int bkc  = (lane >> 3) & 1;

    unsigned aQ  = sb + (unsigned)((w * 16 + arow) * 272 + akc * 16);
    unsigned bKo = (unsigned)(brow * 272 + bkc * 16);
    unsigned bV  = sb + 69632u + (unsigned)(brow * 144 + bkc * 16);
    unsigned aP  = sb + 88064u + (unsigned)((w * 16 + arow) * 144 + akc * 16);

    const unsigned onesf[2] = { 0x3C003C00u, 0x3C003C00u };  // f16 {1,1},{1,1}

    float m0r = -1e30f, m1r = -1e30f;
    float lacc[4] = {};
    float acc[16][4];
    #pragma unroll
    for (int nf = 0; nf < 16; nf++)
        #pragma unroll
        for (int r = 0; r < 4; r++) acc[nf][r] = 0.f;

    int srow = w * 16 + g;

    for (int kt = 0; kt <= ktmax; kt++) {
        asm volatile("cp.async.wait_group 0;\n");   // K[kt] (+V[kt-1]) done
        __syncthreads();                 // all loads visible; buffers free

        // commit {V[kt], K[kt+1]}
        loadV(kt);
        if (kt + 1 <= ktmax) loadK(kt + 1);
        asm volatile("cp.async.commit_group;\n");

        bool active = !(kt == ktmax && w < 4);
        float alpha0 = 1.f, alpha1 = 1.f;
        float sacc[8][4] = {};

        if (active) {
            // ---- S = Q K^T (single-plane f16; log2 domain) ----
            unsigned bK = sb + 34816u + (kt & 1) * 17408u + bKo;
            #pragma unroll
            for (int ks = 0; ks < 8; ks++) {
                unsigned qf[4];
                ldsm4(qf, aQ + ks * 32);
                #pragma unroll
                for (int nblk = 0; nblk < 4; nblk++) {
                    unsigned kf[4];
                    ldsm4(kf, bK + nblk * 4352u + ks * 32);   // 16 rows * 272 B
                    mma_f16(sacc[nblk * 2 + 0], qf, &kf[0]);
                    mma_f16(sacc[nblk * 2 + 1], qf, &kf[2]);
                }
            }

            // ---- causal mask ----
            if (kt >= 2 * qt) {
                int k0 = kt * 64;
                #pragma unroll
                for (int nf = 0; nf < 8; nf++) {
                    int qr = q0 + srow, kc = k0 + nf * 8 + 2 * tc;
                    if (kc     > qr)     sacc[nf][0] = -1e30f;
                    if (kc + 1 > qr)     sacc[nf][1] = -1e30f;
                    if (kc     > qr + 8) sacc[nf][2] = -1e30f;
                    if (kc + 1 > qr + 8) sacc[nf][3] = -1e30f;
                }
            }

            // ---- register softmax (ex2.f16x2); P -> smem ----
            float mx0 = -1e30f, mx1 = -1e30f;
            #pragma unroll
            for (int nf = 0; nf < 8; nf++) {
                mx0 = fmaxf(mx0, fmaxf(sacc[nf][0], sacc[nf][1]));
                mx1 = fmaxf(mx1, fmaxf(sacc[nf][2], sacc[nf][3]));
            }
            mx0 = fmaxf(mx0, __shfl_xor_sync(0xffffffffu, mx0, 1));
            mx0 = fmaxf(mx0, __shfl_xor_sync(0xffffffffu, mx0, 2));
            mx1 = fmaxf(mx1, __shfl_xor_sync(0xffffffffu, mx1, 1));
            mx1 = fmaxf(mx1, __shfl_xor_sync(0xffffffffu, mx1, 2));

            float mn0 = fmaxf(m0r, mx0), mn1 = fmaxf(m1r, mx1);
            alpha0 = ex2f(m0r - mn0);
            alpha1 = ex2f(m1r - mn1);
            m0r = mn0; m1r = mn1;

            unsigned pr0 = sb + 88064u + srow * 144u;
            unsigned pr1 = pr0 + 8 * 144u;
            #pragma unroll
            for (int nf = 0; nf < 8; nf++) {
                unsigned t0 = pack_rn_f16(sacc[nf][0] - mn0, sacc[nf][1] - mn0);
                unsigned t1 = pack_rn_f16(sacc[nf][2] - mn1, sacc[nf][3] - mn1);
                unsigned pk0 = ex2_f16x2(t0);
                unsigned pk1 = ex2_f16x2(t1);
                unsigned wo = (nf * 4 + tc) * 4;
                asm volatile("st.shared.b32 [%0], %1;" :: "r"(pr0 + wo), "r"(pk0));
                asm volatile("st.shared.b32 [%0], %1;" :: "r"(pr1 + wo), "r"(pk1));
            }
            __syncwarp();

            // ---- rescale O and l ----
            #pragma unroll
            for (int nf = 0; nf < 16; nf++) {
                acc[nf][0] *= alpha0; acc[nf][1] *= alpha0;
                acc[nf][2] *= alpha1; acc[nf][3] *= alpha1;
            }
            lacc[0] *= alpha0; lacc[1] *= alpha0;
            lacc[2] *= alpha1; lacc[3] *= alpha1;
        }

        asm volatile("cp.async.wait_group 0;\n");   // V[kt] done
        __syncthreads();                 // all threads' V[kt] visible

        if (active) {
            // ---- O += P V ; l += P·1 ----
            #pragma unroll
            for (int ks = 0; ks < 4; ks++) {
                unsigned phf[4];
                ldsm4(phf, aP + ks * 32);
                mma_f16(lacc, phf, onesf);
                #pragma unroll
                for (int nblk = 0; nblk < 8; nblk++) {
                    unsigned vhf[4];
                    ldsm4(vhf, bV + nblk * 2304u + ks * 32);  // 16 rows * 144 B
                    mma_f16(acc[nblk * 2 + 0], phf, &vhf[0]);
                    mma_f16(acc[nblk * 2 + 1], phf, &vhf[2]);
                }
            }
        }
    }

    // ---- epilogue: write bf16 hi/lo planes directly (GEMM2 A operand) ----
    float inv0 = 1.f / lacc[0];
    float inv1 = 1.f / lacc[2];
    int row = q0 + srow;
    size_t o0 = (size_t)(b * SS + row) * (QDIM / 2) + h * 64;
    size_t o1 = o0 + (size_t)8 * (QDIM / 2);
    #pragma unroll
    for (int nf = 0; nf < 16; nf++) {
        unsigned hi, lo;
        pack_hilo(acc[nf][0] * inv0, acc[nf][1] * inv0, hi, lo);
        oh[o0 + nf * 4 + tc] = hi;
        ol[o0 + nf * 4 + tc] = lo;
        pack_hilo(acc[nf][2] * inv1, acc[nf][3] * inv1, hi, lo);
        oh[o1 + nf * 4 + tc] = hi;
        ol[o1 + nf * 4 + tc] = lo;
    }
}

// ---------------------------------------------------------------------------
extern "C" void kernel_launch(void* const* d_in, const int* in_sizes, int n_in,
                              void* d_out, int out_size)
{
    (void)in_sizes; (void)n_in; (void)out_size;
    const float* x     = (const float*)d_in[0];
    const float* freqs = (const float*)d_in[1];
    const float* Wqkv  = (const float*)d_in[2];
    const float* Wo    = (const float*)d_in[3];
    float* out = (float*)d_out;

    float *qkvp;
    unsigned *xh, *xl, *wqh, *wql, *ah, *al, *woh, *wol;
    unsigned *qh, *kh, *vth;
    cudaGetSymbolAddress((void**)&qkvp, g_qkv);
    cudaGetSymbolAddress((void**)&xh, g_xh);   cudaGetSymbolAddress((void**)&xl, g_xl);
    cudaGetSymbolAddress((void**)&wqh, g_wqh); cudaGetSymbolAddress((void**)&wql, g_wql);
    cudaGetSymbolAddress((void**)&ah, g_ah);   cudaGetSymbolAddress((void**)&al, g_al);
    cudaGetSymbolAddress((void**)&woh, g_woh); cudaGetSymbolAddress((void**)&wol, g_wol);
    cudaGetSymbolAddress((void**)&qh, g_qh);
    cudaGetSymbolAddress((void**)&kh, g_kh);
    cudaGetSymbolAddress((void**)&vth, g_vth);

    cudaFuncSetAttribute(attn_f16_kernel, cudaFuncAttributeMaxDynamicSharedMemorySize,
                         ATT_SMEM_BYTES);
    cudaFuncSetAttribute(gemm_planes_nt, cudaFuncAttributeMaxDynamicSharedMemorySize,
                         GEMM_SMEM_BYTES);

    // 0) split inputs into bf16 hi/lo planes
    {
        int n4;
        n4 = MROWS * DD / 4;
        split_kernel<<<n4 / 256, 256>>>((const float4*)x, (uint2*)xh, (uint2*)xl, n4);
        n4 = QKVD * DD / 4;
        split_kernel<<<n4 / 256, 256>>>((const float4*)Wqkv, (uint2*)wqh, (uint2*)wql, n4);
        n4 = DD * QDIM / 4;
        split_kernel<<<n4 / 256, 256>>>((const float4*)Wo, (uint2*)woh, (uint2*)wol, n4);
    }

    // 1) QKV projection (bf16x3, ldmatrix)
    gemm_planes_nt<<<dim3(QKVD / 128, MROWS / 128), 256, GEMM_SMEM_BYTES>>>(
        xh, xl, wqh, wql, qkvp, MROWS, QKVD, DD);

    // 2) RoPE -> q/k f16 planes (q pre-scaled to log2 domain); V pack (f16)
    rope_qk_kernel<<<(BB * SS * 20 * 64) / 256, 256>>>(qkvp, freqs, qh, kh);
    vpack_kernel<<<(BB * NKVV * HDD * (SS / 2)) / 256, 256>>>(qkvp, vth);

    // 3) causal GQA flash attention -> hi/lo planes directly
    attn_f16_kernel<<<dim3(SS / 128, NHH, BB), 256, ATT_SMEM_BYTES>>>(
        qh, kh, vth, ah, al);

    // 4) output projection (bf16x3, ldmatrix)
    gemm_planes_nt<<<dim3(DD / 128, MROWS / 128), 256, GEMM_SMEM_BYTES>>>(
        ah, al, woh, wol, out, MROWS, DD, QDIM);
}

// round 15
// speedup vs baseline: 1.2302x; 1.0036x over previous
#include <cuda_runtime.h>
#include <cuda_fp16.h>

#define BB 2
#define SS 2048
#define DD 2048
#define NHH 16
#define NKVV 4
#define HDD 128
#define QDIM 2048
#define KVDIM 512
#define QKVD 3072
#define MROWS (BB*SS)   // 4096

#define SCALE_L2E (0.08838834764831845f * 1.44269504088896340f)

// fp32 scratch
__device__ float g_qkv[(size_t)MROWS * QKVD];

// packed bf16 hi/lo planes for projections
__device__ unsigned g_xh[(size_t)MROWS * DD / 2],   g_xl[(size_t)MROWS * DD / 2];
__device__ unsigned g_wqh[(size_t)QKVD * DD / 2],   g_wql[(size_t)QKVD * DD / 2];
__device__ unsigned g_ah[(size_t)MROWS * QDIM / 2], g_al[(size_t)MROWS * QDIM / 2];
__device__ unsigned g_woh[(size_t)DD * QDIM / 2],   g_wol[(size_t)DD * QDIM / 2];

// attention operand planes (q/k/v all single f16 planes)
__device__ unsigned g_qh[(size_t)MROWS * QDIM / 2];
__device__ unsigned g_kh[(size_t)MROWS * KVDIM / 2];
__device__ unsigned g_vth[(size_t)BB * NKVV * HDD * SS / 2];

// ---------------------------------------------------------------------------
// helpers
// ---------------------------------------------------------------------------
__device__ __forceinline__ void mma_bf16(float* c, const unsigned* a, const unsigned* b) {
    asm volatile(
        "mma.sync.aligned.m16n8k16.row.col.f32.bf16.bf16.f32 "
        "{%0,%1,%2,%3},{%4,%5,%6,%7},{%8,%9},{%0,%1,%2,%3};"
        : "+f"(c[0]), "+f"(c[1]), "+f"(c[2]), "+f"(c[3])
        : "r"(a[0]), "r"(a[1]), "r"(a[2]), "r"(a[3]), "r"(b[0]), "r"(b[1]));
}

__device__ __forceinline__ void mma_f16(float* c, const unsigned* a, const unsigned* b) {
    asm volatile(
        "mma.sync.aligned.m16n8k16.row.col.f32.f16.f16.f32 "
        "{%0,%1,%2,%3},{%4,%5,%6,%7},{%8,%9},{%0,%1,%2,%3};"
        : "+f"(c[0]), "+f"(c[1]), "+f"(c[2]), "+f"(c[3])
        : "r"(a[0]), "r"(a[1]), "r"(a[2]), "r"(a[3]), "r"(b[0]), "r"(b[1]));
}

__device__ __forceinline__ void ldsm4(unsigned* r, unsigned addr) {
    asm volatile("ldmatrix.sync.aligned.m8n8.x4.shared.b16 {%0,%1,%2,%3}, [%4];"
                 : "=r"(r[0]), "=r"(r[1]), "=r"(r[2]), "=r"(r[3]) : "r"(addr));
}

__device__ __forceinline__ void cp16u(unsigned smem_dst, const void* gsrc) {
    asm volatile("cp.async.ca.shared.global [%0], [%1], 16;\n" :: "r"(smem_dst), "l"(gsrc));
}

__device__ __forceinline__ unsigned smem_u32(const void* p) {
    return (unsigned)__cvta_generic_to_shared(p);
}

__device__ __forceinline__ void pack_hilo(float p0, float p1, unsigned& hi, unsigned& lo) {
    unsigned u0 = __float_as_uint(p0), u1 = __float_as_uint(p1);
    asm("prmt.b32 %0, %1, %2, 0x7632;" : "=r"(hi) : "r"(u0), "r"(u1));
    float l0 = p0 - __uint_as_float(u0 & 0xffff0000u);
    float l1 = p1 - __uint_as_float(u1 & 0xffff0000u);
    asm("cvt.rn.satfinite.bf16x2.f32 %0, %1, %2;" : "=r"(lo) : "f"(l1), "f"(l0));
}

__device__ __forceinline__ unsigned pack_rn_f16(float p0, float p1) {
    unsigned r;
    asm("cvt.rn.f16x2.f32 %0, %1, %2;" : "=r"(r) : "f"(p1), "f"(p0));
    return r;
}

__device__ __forceinline__ float ex2f(float x) {
    float r;
    asm("ex2.approx.f32 %0, %1;" : "=f"(r) : "f"(x));
    return r;
}

__device__ __forceinline__ unsigned ex2_f16x2(unsigned x) {
    unsigned r;
    asm("ex2.approx.f16x2 %0, %1;" : "=r"(r) : "r"(x));
    return r;
}

// ---------------------------------------------------------------------------
// Split fp32 -> packed bf16 hi/lo planes
// ---------------------------------------------------------------------------
__global__ __launch_bounds__(256) void split_kernel(
    const float4* __restrict__ in, uint2* __restrict__ hi, uint2* __restrict__ lo,
    int n4)
{
    int i = blockIdx.x * blockDim.x + threadIdx.x;
    if (i >= n4) return;
    float4 v = in[i];
    uint2 h, l;
    pack_hilo(v.x, v.y, h.x, l.x);
    pack_hilo(v.z, v.w, h.y, l.y);
    hi[i] = h;
    lo[i] = l;
}

// ---------------------------------------------------------------------------
// Pure-bf16 x3 NT GEMM on pre-split planes, ldmatrix fragment loads.
// mma issued in 3 passes over all 16 accumulators (hi*hi, hi*lo, lo*hi)
// so same-accumulator reuse distance is 16 mmas (hides HMMA f32-acc RAW).
// ---------------------------------------------------------------------------
#define PLANE_W (128 * 20)
#define STAGE_W (4 * PLANE_W)
#define GEMM_SMEM_BYTES (2 * STAGE_W * 4)
#define PLANE_B (PLANE_W * 4)
#define STAGE_B (STAGE_W * 4)

__global__ __launch_bounds__(256, 2) void gemm_planes_nt(
    const unsigned* __restrict__ Ah, const unsigned* __restrict__ Al,
    const unsigned* __restrict__ Bh, const unsigned* __restrict__ Bl,
    float* __restrict__ C, int M, int N, int K)
{
    extern __shared__ unsigned usm[];
    const int KW = K >> 1;

    int tid = threadIdx.x;
    int lane = tid & 31, w = tid >> 5;
    int wm = w >> 2, wn = w & 3;
    int g = lane >> 2, tc = lane & 3;
    int m0 = blockIdx.y * 128, n0 = blockIdx.x * 128;

    int lr = tid >> 2;
    int lw = (tid & 3) * 4;

    const unsigned* gp[4] = {
        Ah + (size_t)(m0 + lr) * KW + lw,
        Al + (size_t)(m0 + lr) * KW + lw,
        Bh + (size_t)(n0 + lr) * KW + lw,
        Bl + (size_t)(n0 + lr) * KW + lw };

    float acc[4][4][4] = {};

    auto load_stage = [&](int t, int buf) {
        unsigned* st = usm + buf * STAGE_W;
        size_t ko = (size_t)t * 16;
        #pragma unroll
        for (int p = 0; p < 4; p++) {
            #pragma unroll
            for (int r2 = 0; r2 < 2; r2++) {
                unsigned* d = st + p * PLANE_W + (lr + r2 * 64) * 20 + lw;
                cp16u((unsigned)__cvta_generic_to_shared(d),
                      gp[p] + (size_t)r2 * 64 * KW + ko);
            }
        }
        asm volatile("cp.async.commit_group;\n");
    };

    unsigned smem_base = smem_u32(usm);
    int arow = lane & 15;
    int akc  = (lane >> 4) & 1;
    int brow = (lane & 7) | (((lane >> 4) & 1) << 3);
    int bkc  = (lane >> 3) & 1;

    unsigned aH = smem_base + 0 * PLANE_B + (unsigned)((wm * 64 + arow) * 80 + akc * 16);
    unsigned aL = aH + PLANE_B;
    unsigned bH = smem_base + 2 * PLANE_B + (unsigned)((wn * 32 + brow) * 80 + bkc * 16);
    unsigned bL = bH + PLANE_B;

    int T = K / 32;
    load_stage(0, 0);

    for (int t = 0; t < T; t++) {
        asm volatile("cp.async.wait_group 0;\n");
        __syncthreads();
        if (t + 1 < T) load_stage(t + 1, (t + 1) & 1);

        unsigned stg = (t & 1) * STAGE_B;

        #pragma unroll
        for (int ks = 0; ks < 2; ks++) {
            unsigned ah[4][4], al[4][4], bhp[2][4], blp[2][4];
            unsigned kso = stg + ks * 32;
            #pragma unroll
            for (int mf = 0; mf < 4; mf++) {
                ldsm4(ah[mf], aH + kso + mf * 1280);
                ldsm4(al[mf], aL + kso + mf * 1280);
            }
            #pragma unroll
            for (int p = 0; p < 2; p++) {
                ldsm4(bhp[p], bH + kso + p * 1280);
                ldsm4(blp[p], bL + kso + p * 1280);
            }
            // pass 1: hi * hi  (16 independent accumulators)
            #pragma unroll
            for (int mf = 0; mf < 4; mf++)
                #pragma unroll
                for (int nf = 0; nf < 4; nf++)
                    mma_bf16(acc[mf][nf], ah[mf], &bhp[nf >> 1][(nf & 1) * 2]);
            // pass 2: hi * lo
            #pragma unroll
            for (int mf = 0; mf < 4; mf++)
                #pragma unroll
                for (int nf = 0; nf < 4; nf++)
                    mma_bf16(acc[mf][nf], ah[mf], &blp[nf >> 1][(nf & 1) * 2]);
            // pass 3: lo * hi
            #pragma unroll
            for (int mf = 0; mf < 4; mf++)
                #pragma unroll
                for (int nf = 0; nf < 4; nf++)
                    mma_bf16(acc[mf][nf], al[mf], &bhp[nf >> 1][(nf & 1) * 2]);
        }
        __syncthreads();
    }

    #pragma unroll
    for (int mf = 0; mf < 4; mf++) {
        #pragma unroll
        for (int nf = 0; nf < 4; nf++) {
            int row = m0 + wm * 64 + mf * 16 + g;
            int col = n0 + wn * 32 + nf * 8 + 2 * tc;
            *(float2*)(C + (size_t)row * N + col) =
                make_float2(acc[mf][nf][0], acc[mf][nf][1]);
            *(float2*)(C + (size_t)(row + 8) * N + col) =
                make_float2(acc[mf][nf][2], acc[mf][nf][3]);
        }
    }
}

// ---------------------------------------------------------------------------
// RoPE on q,k -> single f16 planes. Q pre-scaled by scale*log2e.
// ---------------------------------------------------------------------------
__global__ __launch_bounds__(256) void rope_qk_kernel(
    const float* __restrict__ qkv, const float* __restrict__ freqs,
    unsigned* __restrict__ qh, unsigned* __restrict__ kh)
{
    int idx = blockIdx.x * blockDim.x + threadIdx.x;
    int i    = idx & 63;
    int head = (idx >> 6) % 20;
    int bs   = idx / (64 * 20);
    int s    = bs & (SS - 1);

    int off = (head < NHH) ? head * HDD : QDIM + (head - NHH) * HDD;
    size_t base = (size_t)bs * QKVD + off + 2 * i;
    float t0 = qkv[base], t1 = qkv[base + 1];
    float f0 = freqs[s * HDD + 2 * i];
    float f1 = freqs[s * HDD + 2 * i + 1];
    float r0 = t0 * f1 - t1 * f0;
    float r1 = t0 * f0 + t1 * f1;
    if (head < NHH) {
        size_t o = (size_t)bs * (QDIM / 2) + head * 64 + i;
        qh[o] = pack_rn_f16(r0 * SCALE_L2E, r1 * SCALE_L2E);
    } else {
        size_t o = (size_t)bs * (KVDIM / 2) + (head - NHH) * 64 + i;
        kh[o] = pack_rn_f16(r0, r1);
    }
}

// ---------------------------------------------------------------------------
// V pack + transpose -> single f16 plane, vt[b][kvh][hd][s].
// ---------------------------------------------------------------------------
__global__ __launch_bounds__(256) void vpack_kernel(
    const float* __restrict__ qkv, unsigned* __restrict__ vth)
{
    int idx = blockIdx.x * blockDim.x + threadIdx.x;
    int s2  = idx & (SS / 2 - 1);
    int hd  = (idx >> 10) & (HDD - 1);
    int kvh = (idx >> 17) & (NKVV - 1);
    int b   = idx >> 19;

    const float* src = qkv + (size_t)(b * SS + 2 * s2) * QKVD
                           + QDIM + KVDIM + kvh * HDD + hd;
    size_t o = ((size_t)((b * NKVV + kvh) * HDD + hd)) * (SS / 2) + s2;
    vth[o] = pack_rn_f16(src[0], src[QKVD]);
}

// ---------------------------------------------------------------------------
// Causal flash attention, all-f16 mma (unchanged from R14 — verified).
// ---------------------------------------------------------------------------
#define ATT_SMEM_BYTES 106496

__global__ __launch_bounds__(256, 2) void attn_f16_kernel(
    const unsigned* __restrict__ qh, const unsigned* __restrict__ kh,
    const unsigned* __restrict__ vth,
    unsigned* __restrict__ oh, unsigned* __restrict__ ol)
{
    extern __shared__ __align__(16) unsigned char dynsm[];
    unsigned sb = smem_u32(dynsm);

    int tid = threadIdx.x;
    int lane = tid & 31, w = tid >> 5;
    int g = lane >> 2, tc = lane & 3;
    int qt = (SS / 128 - 1) - blockIdx.x;
    int h  = blockIdx.y, b = blockIdx.z;
    int kvh = h >> 2;
    int q0 = qt * 128;
    int ktmax = 2 * qt + 1;

    auto loadK = [&](int kt) {
        unsigned dst0 = sb + 34816u + (kt & 1) * 17408u;
        #pragma unroll
        for (int e = 0; e < 4; e++) {
            int i = tid + e * 256;
            int r = i >> 4, c = i & 15;
            const unsigned* src = kh
                + (size_t)(b * SS + kt * 64 + r) * (KVDIM / 2) + kvh * 64 + c * 4;
            cp16u(dst0 + r * 272u + c * 16u, src);
        }
    };
    auto loadV = [&](int kt) {
        unsigned dst0 = sb + 69632u;
        #pragma unroll
        for (int e = 0; e < 4; e++) {
            int i = tid + e * 256;
            int r = i >> 3, c = i & 7;
            const unsigned* src = vth
                + ((size_t)((b * NKVV + kvh) * HDD + r)) * (SS / 2) + kt * 32 + c * 4;
            cp16u(dst0 + r * 144u + c * 16u, src);
        }
    };

    // prologue: [Q + K0] as one group
    {
        #pragma unroll
        for (int e = 0; e < 8; e++) {
            int i = tid + e * 256;
            int r = i >> 4, c = i & 15;
            const unsigned* src = qh
                + (size_t)(b * SS + q0 + r) * (QDIM / 2) + h * 64 + c * 4;
            cp16u(sb + r * 272u + c * 16u, src);
        }
        loadK(0);
        asm volatile("cp.async.commit_group;\n");
    }

    int arow = lane & 15;
    int akc  = (lane >> 4) & 1;
    int brow = (lane & 7) | (((lane >> 4) & 1) << 3);
    int bkc  = (lane >> 3) & 1;

    unsigned aQ  = sb + (unsigned)((w * 16 + arow) * 272 + akc * 16);
    unsigned bKo = (unsigned)(brow * 272 + bkc * 16);
    unsigned bV  = sb + 69632u + (unsigned)(brow * 144 + bkc * 16);
    unsigned aP  = sb + 88064u + (unsigned)((w * 16 + arow) * 144 + akc * 16);

    const unsigned onesf[2] = { 0x3C003C00u, 0x3C003C00u };

    float m0r = -1e30f, m1r = -1e30f;
    float lacc[4] = {};
    float acc[16][4];
    #pragma unroll
    for (int nf = 0; nf < 16; nf++)
        #pragma unroll
        for (int r = 0; r < 4; r++) acc[nf][r] = 0.f;

    int srow = w * 16 + g;

    for (int kt = 0; kt <= ktmax; kt++) {
        asm volatile("cp.async.wait_group 0;\n");
        __syncthreads();

        loadV(kt);
        if (kt + 1 <= ktmax) loadK(kt + 1);
        asm volatile("cp.async.commit_group;\n");

        bool active = !(kt == ktmax && w < 4);
        float alpha0 = 1.f, alpha1 = 1.f;
        float sacc[8][4] = {};

        if (active) {
            unsigned bK = sb + 34816u + (kt & 1) * 17408u + bKo;
            #pragma unroll
            for (int ks = 0; ks < 8; ks++) {
                unsigned qf[4];
                ldsm4(qf, aQ + ks * 32);
                #pragma unroll
                for (int nblk = 0; nblk < 4; nblk++) {
                    unsigned kf[4];
                    ldsm4(kf, bK + nblk * 4352u + ks * 32);
                    mma_f16(sacc[nblk * 2 + 0], qf, &kf[0]);
                    mma_f16(sacc[nblk * 2 + 1], qf, &kf[2]);
                }
            }

            if (kt >= 2 * qt) {
                int k0 = kt * 64;
                #pragma unroll
                for (int nf = 0; nf < 8; nf++) {
                    int qr = q0 + srow, kc = k0 + nf * 8 + 2 * tc;
                    if (kc     > qr)     sacc[nf][0] = -1e30f;
                    if (kc + 1 > qr)     sacc[nf][1] = -1e30f;
                    if (kc     > qr + 8) sacc[nf][2] = -1e30f;
                    if (kc + 1 > qr + 8) sacc[nf][3] = -1e30f;
                }
            }

            float mx0 = -1e30f, mx1 = -1e30f;
            #pragma unroll
            for (int nf = 0; nf < 8; nf++) {
                mx0 = fmaxf(mx0, fmaxf(sacc[nf][0], sacc[nf][1]));
                mx1 = fmaxf(mx1, fmaxf(sacc[nf][2], sacc[nf][3]));
            }
            mx0 = fmaxf(mx0, __shfl_xor_sync(0xffffffffu, mx0, 1));
            mx0 = fmaxf(mx0, __shfl_xor_sync(0xffffffffu, mx0, 2));
            mx1 = fmaxf(mx1, __shfl_xor_sync(0xffffffffu, mx1, 1));
            mx1 = fmaxf(mx1, __shfl_xor_sync(0xffffffffu, mx1, 2));

            float mn0 = fmaxf(m0r, mx0), mn1 = fmaxf(m1r, mx1);
            alpha0 = ex2f(m0r - mn0);
            alpha1 = ex2f(m1r - mn1);
            m0r = mn0; m1r = mn1;

            unsigned pr0 = sb + 88064u + srow * 144u;
            unsigned pr1 = pr0 + 8 * 144u;
            #pragma unroll
            for (int nf = 0; nf < 8; nf++) {
                unsigned t0 = pack_rn_f16(sacc[nf][0] - mn0, sacc[nf][1] - mn0);
                unsigned t1 = pack_rn_f16(sacc[nf][2] - mn1, sacc[nf][3] - mn1);
                unsigned pk0 = ex2_f16x2(t0);
                unsigned pk1 = ex2_f16x2(t1);
                unsigned wo = (nf * 4 + tc) * 4;
                asm volatile("st.shared.b32 [%0], %1;" :: "r"(pr0 + wo), "r"(pk0));
                asm volatile("st.shared.b32 [%0], %1;" :: "r"(pr1 + wo), "r"(pk1));
            }
            __syncwarp();

            #pragma unroll
            for (int nf = 0; nf < 16; nf++) {
                acc[nf][0] *= alpha0; acc[nf][1] *= alpha0;
                acc[nf][2] *= alpha1; acc[nf][3] *= alpha1;
            }
            lacc[0] *= alpha0; lacc[1] *= alpha0;
            lacc[2] *= alpha1; lacc[3] *= alpha1;
        }

        asm volatile("cp.async.wait_group 0;\n");
        __syncthreads();

        if (active) {
            #pragma unroll
            for (int ks = 0; ks < 4; ks++) {
                unsigned phf[4];
                ldsm4(phf, aP + ks * 32);
                mma_f16(lacc, phf, onesf);
                #pragma unroll
                for (int nblk = 0; nblk < 8; nblk++) {
                    unsigned vhf[4];
                    ldsm4(vhf, bV + nblk * 2304u + ks * 32);
                    mma_f16(acc[nblk * 2 + 0], phf, &vhf[0]);
                    mma_f16(acc[nblk * 2 + 1], phf, &vhf[2]);
                }
            }
        }
    }

    // epilogue: write bf16 hi/lo planes directly (GEMM2 A operand)
    float inv0 = 1.f / lacc[0];
    float inv1 = 1.f / lacc[2];
    int row = q0 + srow;
    size_t o0 = (size_t)(b * SS + row) * (QDIM / 2) + h * 64;
    size_t o1 = o0 + (size_t)8 * (QDIM / 2);
    #pragma unroll
    for (int nf = 0; nf < 16; nf++) {
        unsigned hi, lo;
        pack_hilo(acc[nf][0] * inv0, acc[nf][1] * inv0, hi, lo);
        oh[o0 + nf * 4 + tc] = hi;
        ol[o0 + nf * 4 + tc] = lo;
        pack_hilo(acc[nf][2] * inv1, acc[nf][3] * inv1, hi, lo);
        oh[o1 + nf * 4 + tc] = hi;
        ol[o1 + nf * 4 + tc] = lo;
    }
}

// ---------------------------------------------------------------------------
extern "C" void kernel_launch(void* const* d_in, const int* in_sizes, int n_in,
                              void* d_out, int out_size)
{
    (void)in_sizes; (void)n_in; (void)out_size;
    const float* x     = (const float*)d_in[0];
    const float* freqs = (const float*)d_in[1];
    const float* Wqkv  = (const float*)d_in[2];
    const float* Wo    = (const float*)d_in[3];
    float* out = (float*)d_out;

    float *qkvp;
    unsigned *xh, *xl, *wqh, *wql, *ah, *al, *woh, *wol;
    unsigned *qh, *kh, *vth;
    cudaGetSymbolAddress((void**)&qkvp, g_qkv);
    cudaGetSymbolAddress((void**)&xh, g_xh);   cudaGetSymbolAddress((void**)&xl, g_xl);
    cudaGetSymbolAddress((void**)&wqh, g_wqh); cudaGetSymbolAddress((void**)&wql, g_wql);
    cudaGetSymbolAddress((void**)&ah, g_ah);   cudaGetSymbolAddress((void**)&al, g_al);
    cudaGetSymbolAddress((void**)&woh, g_woh); cudaGetSymbolAddress((void**)&wol, g_wol);
    cudaGetSymbolAddress((void**)&qh, g_qh);
    cudaGetSymbolAddress((void**)&kh, g_kh);
    cudaGetSymbolAddress((void**)&vth, g_vth);

    cudaFuncSetAttribute(attn_f16_kernel, cudaFuncAttributeMaxDynamicSharedMemorySize,
                         ATT_SMEM_BYTES);
    cudaFuncSetAttribute(gemm_planes_nt, cudaFuncAttributeMaxDynamicSharedMemorySize,
                         GEMM_SMEM_BYTES);

    // 0) split inputs into bf16 hi/lo planes
    {
        int n4;
        n4 = MROWS * DD / 4;
        split_kernel<<<n4 / 256, 256>>>((const float4*)x, (uint2*)xh, (uint2*)xl, n4);
        n4 = QKVD * DD / 4;
        split_kernel<<<n4 / 256, 256>>>((const float4*)Wqkv, (uint2*)wqh, (uint2*)wql, n4);
        n4 = DD * QDIM / 4;
        split_kernel<<<n4 / 256, 256>>>((const float4*)Wo, (uint2*)woh, (uint2*)wol, n4);
    }

    // 1) QKV projection (bf16x3, ldmatrix, 3-pass mma order)
    gemm_planes_nt<<<dim3(QKVD / 128, MROWS / 128), 256, GEMM_SMEM_BYTES>>>(
        xh, xl, wqh, wql, qkvp, MROWS, QKVD, DD);

    // 2) RoPE -> q/k f16 planes (q pre-scaled to log2 domain); V pack (f16)
    rope_qk_kernel<<<(BB * SS * 20 * 64) / 256, 256>>>(qkvp, freqs, qh, kh);
    vpack_kernel<<<(BB * NKVV * HDD * (SS / 2)) / 256, 256>>>(qkvp, vth);

    // 3) causal GQA flash attention -> hi/lo planes directly
    attn_f16_kernel<<<dim3(SS / 128, NHH, BB), 256, ATT_SMEM_BYTES>>>(
        qh, kh, vth, ah, al);

    // 4) output projection (bf16x3, ldmatrix, 3-pass mma order)
    gemm_planes_nt<<<dim3(DD / 128, MROWS / 128), 256, GEMM_SMEM_BYTES>>>(
        ah, al, woh, wol, out, MROWS, DD, QDIM);
}

// round 17
// speedup vs baseline: 1.2533x; 1.0188x over previous
#include <cuda_runtime.h>
#include <cuda_fp16.h>

#define BB 2
#define SS 2048
#define DD 2048
#define NHH 16
#define NKVV 4
#define HDD 128
#define QDIM 2048
#define KVDIM 512
#define QKVD 3072
#define MROWS (BB*SS)   // 4096

#define SCALE_L2E (0.08838834764831845f * 1.44269504088896340f)

// fp32 scratch
__device__ float g_qkv[(size_t)MROWS * QKVD];

// packed bf16 hi/lo planes for projections
__device__ unsigned g_xh[(size_t)MROWS * DD / 2],   g_xl[(size_t)MROWS * DD / 2];
__device__ unsigned g_wqh[(size_t)QKVD * DD / 2],   g_wql[(size_t)QKVD * DD / 2];
__device__ unsigned g_ah[(size_t)MROWS * QDIM / 2], g_al[(size_t)MROWS * QDIM / 2];
__device__ unsigned g_woh[(size_t)DD * QDIM / 2],   g_wol[(size_t)DD * QDIM / 2];

// attention operand planes (q/k/v all single f16 planes)
__device__ unsigned g_qh[(size_t)MROWS * QDIM / 2];
__device__ unsigned g_kh[(size_t)MROWS * KVDIM / 2];
__device__ unsigned g_vth[(size_t)BB * NKVV * HDD * SS / 2];

// ---------------------------------------------------------------------------
// helpers
// ---------------------------------------------------------------------------
__device__ __forceinline__ void mma_bf16(float* c, const unsigned* a, const unsigned* b) {
    asm volatile(
        "mma.sync.aligned.m16n8k16.row.col.f32.bf16.bf16.f32 "
        "{%0,%1,%2,%3},{%4,%5,%6,%7},{%8,%9},{%0,%1,%2,%3};"
        : "+f"(c[0]), "+f"(c[1]), "+f"(c[2]), "+f"(c[3])
        : "r"(a[0]), "r"(a[1]), "r"(a[2]), "r"(a[3]), "r"(b[0]), "r"(b[1]));
}

__device__ __forceinline__ void mma_f16(float* c, const unsigned* a, const unsigned* b) {
    asm volatile(
        "mma.sync.aligned.m16n8k16.row.col.f32.f16.f16.f32 "
        "{%0,%1,%2,%3},{%4,%5,%6,%7},{%8,%9},{%0,%1,%2,%3};"
        : "+f"(c[0]), "+f"(c[1]), "+f"(c[2]), "+f"(c[3])
        : "r"(a[0]), "r"(a[1]), "r"(a[2]), "r"(a[3]), "r"(b[0]), "r"(b[1]));
}

__device__ __forceinline__ void ldsm4(unsigned* r, unsigned addr) {
    asm volatile("ldmatrix.sync.aligned.m8n8.x4.shared.b16 {%0,%1,%2,%3}, [%4];"
                 : "=r"(r[0]), "=r"(r[1]), "=r"(r[2]), "=r"(r[3]) : "r"(addr));
}

__device__ __forceinline__ void cp16u(unsigned smem_dst, const void* gsrc) {
    asm volatile("cp.async.ca.shared.global [%0], [%1], 16;\n" :: "r"(smem_dst), "l"(gsrc));
}

__device__ __forceinline__ unsigned smem_u32(const void* p) {
    return (unsigned)__cvta_generic_to_shared(p);
}

__device__ __forceinline__ void pack_hilo(float p0, float p1, unsigned& hi, unsigned& lo) {
    unsigned u0 = __float_as_uint(p0), u1 = __float_as_uint(p1);
    asm("prmt.b32 %0, %1, %2, 0x7632;" : "=r"(hi) : "r"(u0), "r"(u1));
    float l0 = p0 - __uint_as_float(u0 & 0xffff0000u);
    float l1 = p1 - __uint_as_float(u1 & 0xffff0000u);
    asm("cvt.rn.satfinite.bf16x2.f32 %0, %1, %2;" : "=r"(lo) : "f"(l1), "f"(l0));
}

__device__ __forceinline__ unsigned pack_rn_f16(float p0, float p1) {
    unsigned r;
    asm("cvt.rn.f16x2.f32 %0, %1, %2;" : "=r"(r) : "f"(p1), "f"(p0));
    return r;
}

__device__ __forceinline__ float ex2f(float x) {
    float r;
    asm("ex2.approx.f32 %0, %1;" : "=f"(r) : "f"(x));
    return r;
}

__device__ __forceinline__ unsigned ex2_f16x2(unsigned x) {
    unsigned r;
    asm("ex2.approx.f16x2 %0, %1;" : "=r"(r) : "r"(x));
    return r;
}

// ---------------------------------------------------------------------------
// Split fp32 -> packed bf16 hi/lo planes
// ---------------------------------------------------------------------------
__global__ __launch_bounds__(256) void split_kernel(
    const float4* __restrict__ in, uint2* __restrict__ hi, uint2* __restrict__ lo,
    int n4)
{
    int i = blockIdx.x * blockDim.x + threadIdx.x;
    if (i >= n4) return;
    float4 v = in[i];
    uint2 h, l;
    pack_hilo(v.x, v.y, h.x, l.x);
    pack_hilo(v.z, v.w, h.y, l.y);
    hi[i] = h;
    lo[i] = l;
}

// ---------------------------------------------------------------------------
// bf16x3 NT GEMM, CTA tile 128x256, 8 warps (2x4), warp tile 64x64.
// acc[4][8]: full 64 M-rows per warp (R16 bug: only covered 32).
// smem/stage: [Ah 128x20w @0][Al @2560w][Bh 256x20w @5120w][Bl @10240w].
// ---------------------------------------------------------------------------
#define GSTG_W 15360
#define GEMM_SMEM_BYTES (2 * GSTG_W * 4)   // 122880

__global__ __launch_bounds__(256, 1) void gemm_planes_nt(
    const unsigned* __restrict__ Ah, const unsigned* __restrict__ Al,
    const unsigned* __restrict__ Bh, const unsigned* __restrict__ Bl,
    float* __restrict__ C, int M, int N, int K)
{
    extern __shared__ unsigned usm[];
    const int KW = K >> 1;

    int tid = threadIdx.x;
    int lane = tid & 31, w = tid >> 5;
    int wm = w >> 2, wn = w & 3;            // 2 x 4 warp grid
    int g = lane >> 2, tc = lane & 3;
    int m0 = blockIdx.y * 128, n0 = blockIdx.x * 256;

    int lr = tid >> 2;            // 0..63
    int lw = (tid & 3) * 4;       // word offset 0,4,8,12

    const unsigned* gpA[2] = {
        Ah + (size_t)(m0 + lr) * KW + lw,
        Al + (size_t)(m0 + lr) * KW + lw };
    const unsigned* gpB[2] = {
        Bh + (size_t)(n0 + lr) * KW + lw,
        Bl + (size_t)(n0 + lr) * KW + lw };

    float acc[4][8][4] = {};

    auto load_stage = [&](int t, int buf) {
        unsigned* st = usm + buf * GSTG_W;
        size_t ko = (size_t)t * 16;
        #pragma unroll
        for (int p = 0; p < 2; p++) {
            #pragma unroll
            for (int r2 = 0; r2 < 2; r2++) {      // A: 128 rows
                unsigned* d = st + p * 2560 + (lr + r2 * 64) * 20 + lw;
                cp16u((unsigned)__cvta_generic_to_shared(d),
                      gpA[p] + (size_t)r2 * 64 * KW + ko);
            }
        }
        #pragma unroll
        for (int p = 0; p < 2; p++) {
            #pragma unroll
            for (int r2 = 0; r2 < 4; r2++) {      // B: 256 rows
                unsigned* d = st + 5120 + p * 5120 + (lr + r2 * 64) * 20 + lw;
                cp16u((unsigned)__cvta_generic_to_shared(d),
                      gpB[p] + (size_t)r2 * 64 * KW + ko);
            }
        }
        asm volatile("cp.async.commit_group;\n");
    };

    unsigned smem_base = smem_u32(usm);
    int arow = lane & 15;
    int akc  = (lane >> 4) & 1;
    int brow = (lane & 7) | (((lane >> 4) & 1) << 3);
    int bkc  = (lane >> 3) & 1;

    unsigned aH = smem_base + (unsigned)((wm * 64 + arow) * 80 + akc * 16);
    unsigned bH = smem_base + 20480u + (unsigned)((wn * 64 + brow) * 80 + bkc * 16);

    int T = K / 32;
    load_stage(0, 0);

    for (int t = 0; t < T; t++) {
        asm volatile("cp.async.wait_group 0;\n");
        __syncthreads();
        if (t + 1 < T) load_stage(t + 1, (t + 1) & 1);

        unsigned stg = (t & 1) * (GSTG_W * 4);

        #pragma unroll
        for (int ks = 0; ks < 2; ks++) {
            unsigned kso = stg + ks * 32;
            unsigned ah[4][4], al[4][4], bh[4][4];
            #pragma unroll
            for (int mf = 0; mf < 4; mf++) {
                ldsm4(ah[mf], aH + kso + mf * 1280);
                ldsm4(al[mf], aH + 10240u + kso + mf * 1280);
            }
            #pragma unroll
            for (int nb = 0; nb < 4; nb++)
                ldsm4(bh[nb], bH + kso + nb * 1280);

            // pass 1: hi * hi
            #pragma unroll
            for (int mf = 0; mf < 4; mf++)
                #pragma unroll
                for (int nf = 0; nf < 8; nf++)
                    mma_bf16(acc[mf][nf], ah[mf], &bh[nf >> 1][(nf & 1) * 2]);
            // pass 2: lo * hi (bh still live)
            #pragma unroll
            for (int mf = 0; mf < 4; mf++)
                #pragma unroll
                for (int nf = 0; nf < 8; nf++)
                    mma_bf16(acc[mf][nf], al[mf], &bh[nf >> 1][(nf & 1) * 2]);
            // pass 3: hi * lo (bh dead, bl loaded now)
            unsigned bl[4][4];
            #pragma unroll
            for (int nb = 0; nb < 4; nb++)
                ldsm4(bl[nb], bH + 20480u + kso + nb * 1280);
            #pragma unroll
            for (int mf = 0; mf < 4; mf++)
                #pragma unroll
                for (int nf = 0; nf < 8; nf++)
                    mma_bf16(acc[mf][nf], ah[mf], &bl[nf >> 1][(nf & 1) * 2]);
        }
        __syncthreads();
    }

    #pragma unroll
    for (int mf = 0; mf < 4; mf++) {
        #pragma unroll
        for (int nf = 0; nf < 8; nf++) {
            int row = m0 + wm * 64 + mf * 16 + g;
            int col = n0 + wn * 64 + nf * 8 + 2 * tc;
            *(float2*)(C + (size_t)row * N + col) =
                make_float2(acc[mf][nf][0], acc[mf][nf][1]);
            *(float2*)(C + (size_t)(row + 8) * N + col) =
                make_float2(acc[mf][nf][2], acc[mf][nf][3]);
        }
    }
}

// ---------------------------------------------------------------------------
// RoPE on q,k -> single f16 planes. Q pre-scaled by scale*log2e.
// ---------------------------------------------------------------------------
__global__ __launch_bounds__(256) void rope_qk_kernel(
    const float* __restrict__ qkv, const float* __restrict__ freqs,
    unsigned* __restrict__ qh, unsigned* __restrict__ kh)
{
    int idx = blockIdx.x * blockDim.x + threadIdx.x;
    int i    = idx & 63;
    int head = (idx >> 6) % 20;
    int bs   = idx / (64 * 20);
    int s    = bs & (SS - 1);

    int off = (head < NHH) ? head * HDD : QDIM + (head - NHH) * HDD;
    size_t base = (size_t)bs * QKVD + off + 2 * i;
    float t0 = qkv[base], t1 = qkv[base + 1];
    float f0 = freqs[s * HDD + 2 * i];
    float f1 = freqs[s * HDD + 2 * i + 1];
    float r0 = t0 * f1 - t1 * f0;
    float r1 = t0 * f0 + t1 * f1;
    if (head < NHH) {
        size_t o = (size_t)bs * (QDIM / 2) + head * 64 + i;
        qh[o] = pack_rn_f16(r0 * SCALE_L2E, r1 * SCALE_L2E);
    } else {
        size_t o = (size_t)bs * (KVDIM / 2) + (head - NHH) * 64 + i;
        kh[o] = pack_rn_f16(r0, r1);
    }
}

// ---------------------------------------------------------------------------
// V pack + transpose -> single f16 plane, vt[b][kvh][hd][s].
// ---------------------------------------------------------------------------
__global__ __launch_bounds__(256) void vpack_kernel(
    const float* __restrict__ qkv, unsigned* __restrict__ vth)
{
    int idx = blockIdx.x * blockDim.x + threadIdx.x;
    int s2  = idx & (SS / 2 - 1);
    int hd  = (idx >> 10) & (HDD - 1);
    int kvh = (idx >> 17) & (NKVV - 1);
    int b   = idx >> 19;

    const float* src = qkv + (size_t)(b * SS + 2 * s2) * QKVD
                           + QDIM + KVDIM + kvh * HDD + hd;
    size_t o = ((size_t)((b * NKVV + kvh) * HDD + hd)) * (SS / 2) + s2;
    vth[o] = pack_rn_f16(src[0], src[QKVD]);
}

// ---------------------------------------------------------------------------
// Causal flash attention, all-f16 mma (unchanged from R14 — verified).
// ---------------------------------------------------------------------------
#define ATT_SMEM_BYTES 106496

__global__ __launch_bounds__(256, 2) void attn_f16_kernel(
    const unsigned* __restrict__ qh, const unsigned* __restrict__ kh,
    const unsigned* __restrict__ vth,
    unsigned* __restrict__ oh, unsigned* __restrict__ ol)
{
    extern __shared__ __align__(16) unsigned char dynsm[];
    unsigned sb = smem_u32(dynsm);

    int tid = threadIdx.x;
    int lane = tid & 31, w = tid >> 5;
    int g = lane >> 2, tc = lane & 3;
    int qt = (SS / 128 - 1) - blockIdx.x;
    int h  = blockIdx.y, b = blockIdx.z;
    int kvh = h >> 2;
    int q0 = qt * 128;
    int ktmax = 2 * qt + 1;

    auto loadK = [&](int kt) {
        unsigned dst0 = sb + 34816u + (kt & 1) * 17408u;
        #pragma unroll
        for (int e = 0; e < 4; e++) {
            int i = tid + e * 256;
            int r = i >> 4, c = i & 15;
            const unsigned* src = kh
                + (size_t)(b * SS + kt * 64 + r) * (KVDIM / 2) + kvh * 64 + c * 4;
            cp16u(dst0 + r * 272u + c * 16u, src);
        }
    };
    auto loadV = [&](int kt) {
        unsigned dst0 = sb + 69632u;
        #pragma unroll
        for (int e = 0; e < 4; e++) {
            int i = tid + e * 256;
            int r = i >> 3, c = i & 7;
            const unsigned* src = vth
                + ((size_t)((b * NKVV + kvh) * HDD + r)) * (SS / 2) + kt * 32 + c * 4;
            cp16u(dst0 + r * 144u + c * 16u, src);
        }
    };

    // prologue: [Q + K0] as one group
    {
        #pragma unroll
        for (int e = 0; e < 8; e++) {
            int i = tid + e * 256;
            int r = i >> 4, c = i & 15;
            const unsigned* src = qh
                + (size_t)(b * SS + q0 + r) * (QDIM / 2) + h * 64 + c * 4;
            cp16u(sb + r * 272u + c * 16u, src);
        }
        loadK(0);
        asm volatile("cp.async.commit_group;\n");
    }

    int arow = lane & 15;
    int akc  = (lane >> 4) & 1;
    int brow = (lane & 7) | (((lane >> 4) & 1) << 3);
    int bkc  = (lane >> 3) & 1;

    unsigned aQ  = sb + (unsigned)((w * 16 + arow) * 272 + akc * 16);
    unsigned bKo = (unsigned)(brow * 272 + bkc * 16);
    unsigned bV  = sb + 69632u + (unsigned)(brow * 144 + bkc * 16);
    unsigned aP  = sb + 88064u + (unsigned)((w * 16 + arow) * 144 + akc * 16);

    const unsigned onesf[2] = { 0x3C003C00u, 0x3C003C00u };

    float m0r = -1e30f, m1r = -1e30f;
    float lacc[4] = {};
    float acc[16][4];
    #pragma unroll
    for (int nf = 0; nf < 16; nf++)
        #pragma unroll
        for (int r = 0; r < 4; r++) acc[nf][r] = 0.f;

    int srow = w * 16 + g;

    for (int kt = 0; kt <= ktmax; kt++) {
        asm volatile("cp.async.wait_group 0;\n");
        __syncthreads();

        loadV(kt);
        if (kt + 1 <= ktmax) loadK(kt + 1);
        asm volatile("cp.async.commit_group;\n");

        bool active = !(kt == ktmax && w < 4);
        float alpha0 = 1.f, alpha1 = 1.f;
        float sacc[8][4] = {};

        if (active) {
            unsigned bK = sb + 34816u + (kt & 1) * 17408u + bKo;
            #pragma unroll
            for (int ks = 0; ks < 8; ks++) {
                unsigned qf[4];
                ldsm4(qf, aQ + ks * 32);
                #pragma unroll
                for (int nblk = 0; nblk < 4; nblk++) {
                    unsigned kf[4];
                    ldsm4(kf, bK + nblk * 4352u + ks * 32);
                    mma_f16(sacc[nblk * 2 + 0], qf, &kf[0]);
                    mma_f16(sacc[nblk * 2 + 1], qf, &kf[2]);
                }
            }

            if (kt >= 2 * qt) {
                int k0 = kt * 64;
                #pragma unroll
                for (int nf = 0; nf < 8; nf++) {
                    int qr = q0 + srow, kc = k0 + nf * 8 + 2 * tc;
                    if (kc     > qr)     sacc[nf][0] = -1e30f;
                    if (kc + 1 > qr)     sacc[nf][1] = -1e30f;
                    if (kc     > qr + 8) sacc[nf][2] = -1e30f;
                    if (kc + 1 > qr + 8) sacc[nf][3] = -1e30f;
                }
            }

            float mx0 = -1e30f, mx1 = -1e30f;
            #pragma unroll
            for (int nf = 0; nf < 8; nf++) {
                mx0 = fmaxf(mx0, fmaxf(sacc[nf][0], sacc[nf][1]));
                mx1 = fmaxf(mx1, fmaxf(sacc[nf][2], sacc[nf][3]));
            }
            mx0 = fmaxf(mx0, __shfl_xor_sync(0xffffffffu, mx0, 1));
            mx0 = fmaxf(mx0, __shfl_xor_sync(0xffffffffu, mx0, 2));
            mx1 = fmaxf(mx1, __shfl_xor_sync(0xffffffffu, mx1, 1));
            mx1 = fmaxf(mx1, __shfl_xor_sync(0xffffffffu, mx1, 2));

            float mn0 = fmaxf(m0r, mx0), mn1 = fmaxf(m1r, mx1);
            alpha0 = ex2f(m0r - mn0);
            alpha1 = ex2f(m1r - mn1);
            m0r = mn0; m1r = mn1;

            unsigned pr0 = sb + 88064u + srow * 144u;
            unsigned pr1 = pr0 + 8 * 144u;
            #pragma unroll
            for (int nf = 0; nf < 8; nf++) {
                unsigned t0 = pack_rn_f16(sacc[nf][0] - mn0, sacc[nf][1] - mn0);
                unsigned t1 = pack_rn_f16(sacc[nf][2] - mn1, sacc[nf][3] - mn1);
                unsigned pk0 = ex2_f16x2(t0);
                unsigned pk1 = ex2_f16x2(t1);
                unsigned wo = (nf * 4 + tc) * 4;
                asm volatile("st.shared.b32 [%0], %1;" :: "r"(pr0 + wo), "r"(pk0));
                asm volatile("st.shared.b32 [%0], %1;" :: "r"(pr1 + wo), "r"(pk1));
            }
            __syncwarp();

            #pragma unroll
            for (int nf = 0; nf < 16; nf++) {
                acc[nf][0] *= alpha0; acc[nf][1] *= alpha0;
                acc[nf][2] *= alpha1; acc[nf][3] *= alpha1;
            }
            lacc[0] *= alpha0; lacc[1] *= alpha0;
            lacc[2] *= alpha1; lacc[3] *= alpha1;
        }

        asm volatile("cp.async.wait_group 0;\n");
        __syncthreads();

        if (active) {
            #pragma unroll
            for (int ks = 0; ks < 4; ks++) {
                unsigned phf[4];
                ldsm4(phf, aP + ks * 32);
                mma_f16(lacc, phf, onesf);
                #pragma unroll
                for (int nblk = 0; nblk < 8; nblk++) {
                    unsigned vhf[4];
                    ldsm4(vhf, bV + nblk * 2304u + ks * 32);
                    mma_f16(acc[nblk * 2 + 0], phf, &vhf[0]);
                    mma_f16(acc[nblk * 2 + 1], phf, &vhf[2]);
                }
            }
        }
    }

    // epilogue: write bf16 hi/lo planes directly (GEMM2 A operand)
    float inv0 = 1.f / lacc[0];
    float inv1 = 1.f / lacc[2];
    int row = q0 + srow;
    size_t o0 = (size_t)(b * SS + row) * (QDIM / 2) + h * 64;
    size_t o1 = o0 + (size_t)8 * (QDIM / 2);
    #pragma unroll
    for (int nf = 0; nf < 16; nf++) {
        unsigned hi, lo;
        pack_hilo(acc[nf][0] * inv0, acc[nf][1] * inv0, hi, lo);
        oh[o0 + nf * 4 + tc] = hi;
        ol[o0 + nf * 4 + tc] = lo;
        pack_hilo(acc[nf][2] * inv1, acc[nf][3] * inv1, hi, lo);
        oh[o1 + nf * 4 + tc] = hi;
        ol[o1 + nf * 4 + tc] = lo;
    }
}

// ---------------------------------------------------------------------------
extern "C" void kernel_launch(void* const* d_in, const int* in_sizes, int n_in,
                              void* d_out, int out_size)
{
    (void)in_sizes; (void)n_in; (void)out_size;
    const float* x     = (const float*)d_in[0];
    const float* freqs = (const float*)d_in[1];
    const float* Wqkv  = (const float*)d_in[2];
    const float* Wo    = (const float*)d_in[3];
    float* out = (float*)d_out;

    float *qkvp;
    unsigned *xh, *xl, *wqh, *wql, *ah, *al, *woh, *wol;
    unsigned *qh, *kh, *vth;
    cudaGetSymbolAddress((void**)&qkvp, g_qkv);
    cudaGetSymbolAddress((void**)&xh, g_xh);   cudaGetSymbolAddress((void**)&xl, g_xl);
    cudaGetSymbolAddress((void**)&wqh, g_wqh); cudaGetSymbolAddress((void**)&wql, g_wql);
    cudaGetSymbolAddress((void**)&ah, g_ah);   cudaGetSymbolAddress((void**)&al, g_al);
    cudaGetSymbolAddress((void**)&woh, g_woh); cudaGetSymbolAddress((void**)&wol, g_wol);
    cudaGetSymbolAddress((void**)&qh, g_qh);
    cudaGetSymbolAddress((void**)&kh, g_kh);
    cudaGetSymbolAddress((void**)&vth, g_vth);

    cudaFuncSetAttribute(attn_f16_kernel, cudaFuncAttributeMaxDynamicSharedMemorySize,
                         ATT_SMEM_BYTES);
    cudaFuncSetAttribute(gemm_planes_nt, cudaFuncAttributeMaxDynamicSharedMemorySize,
                         GEMM_SMEM_BYTES);

    // 0) split inputs into bf16 hi/lo planes
    {
        int n4;
        n4 = MROWS * DD / 4;
        split_kernel<<<n4 / 256, 256>>>((const float4*)x, (uint2*)xh, (uint2*)xl, n4);
        n4 = QKVD * DD / 4;
        split_kernel<<<n4 / 256, 256>>>((const float4*)Wqkv, (uint2*)wqh, (uint2*)wql, n4);
        n4 = DD * QDIM / 4;
        split_kernel<<<n4 / 256, 256>>>((const float4*)Wo, (uint2*)woh, (uint2*)wol, n4);
    }

    // 1) QKV projection (bf16x3, 128x256 CTA tile)
    gemm_planes_nt<<<dim3(QKVD / 256, MROWS / 128), 256, GEMM_SMEM_BYTES>>>(
        xh, xl, wqh, wql, qkvp, MROWS, QKVD, DD);

    // 2) RoPE -> q/k f16 planes (log2 domain); V pack (f16)
    rope_qk_kernel<<<(BB * SS * 20 * 64) / 256, 256>>>(qkvp, freqs, qh, kh);
    vpack_kernel<<<(BB * NKVV * HDD * (SS / 2)) / 256, 256>>>(qkvp, vth);

    // 3) causal GQA flash attention -> hi/lo planes directly
    attn_f16_kernel<<<dim3(SS / 128, NHH, BB), 256, ATT_SMEM_BYTES>>>(
        qh, kh, vth, ah, al);

    // 4) output projection (bf16x3, 128x256 CTA tile)
    gemm_planes_nt<<<dim3(DD / 256, MROWS / 128), 256, GEMM_SMEM_BYTES>>>(
        ah, al, woh, wol, out, MROWS, DD, QDIM);
}